// round 1
// baseline (speedup 1.0000x reference)
#include <cuda_runtime.h>
#include <math.h>

#define Bb 2
#define Tt 16
#define Hh 56
#define Ww 56
#define Cc 128
#define HID 512
#define NPTS (Bb*Tt*Hh*Ww)          /* 100352 */
#define TOT  (NPTS*Cc)              /* 12845056 */
#define HWC  (Hh*Ww*Cc)             /* 401408 */
#define KTAPS 245                   /* 5*7*7 */

// Scratch (allocation-free: __device__ globals)
__device__ float g_bufA[TOT];   // gate_proj  -> later exp(log_h)
__device__ float g_bufB[TOT];   // hidden_proj -> later xn (post-LN)
__device__ float g_bufC[TOT];   // gate_spatial
__device__ float g_bufD[TOT];   // hidden_spatial
__device__ float g_kT[2][KTAPS*Cc]; // kernels transposed to [tap][c]

// ---------------------------------------------------------------------------
// K0: transpose conv kernels (C,5,7,7) -> (5,7,7,C) for coalesced tap loads
// ---------------------------------------------------------------------------
__global__ void k_transpose_kernels(const float* __restrict__ gk,
                                    const float* __restrict__ hk) {
    int idx = blockIdx.x * blockDim.x + threadIdx.x;
    if (idx >= 2 * Cc * KTAPS) return;
    int which = idx / (Cc * KTAPS);
    int rem   = idx - which * (Cc * KTAPS);
    int c = rem / KTAPS;
    int r = rem - c * KTAPS;
    const float* src = which ? hk : gk;
    g_kT[which][r * Cc + c] = src[rem];
}

// ---------------------------------------------------------------------------
// K1: dual projection  gateP = x@Wg + bg,  hiddenP = x@Wh + bh
// block = 128 threads (one output channel each), 8 rows per block
// ---------------------------------------------------------------------------
__global__ void k_proj(const float* __restrict__ x,
                       const float* __restrict__ Wg, const float* __restrict__ bg,
                       const float* __restrict__ Wh, const float* __restrict__ bh) {
    __shared__ float xs[8 * Cc];
    int c = threadIdx.x;
    size_t row0 = (size_t)blockIdx.x * 8;
    #pragma unroll
    for (int p = 0; p < 8; p++) xs[p * Cc + c] = x[(row0 + p) * Cc + c];
    __syncthreads();
    float ag[8], ah[8];
    float bgv = bg[c], bhv = bh[c];
    #pragma unroll
    for (int p = 0; p < 8; p++) { ag[p] = bgv; ah[p] = bhv; }
    for (int k = 0; k < Cc; k++) {
        float wg = Wg[k * Cc + c];
        float wh = Wh[k * Cc + c];
        #pragma unroll
        for (int p = 0; p < 8; p++) {
            float xv = xs[p * Cc + k];
            ag[p] = fmaf(xv, wg, ag[p]);
            ah[p] = fmaf(xv, wh, ah[p]);
        }
    }
    #pragma unroll
    for (int p = 0; p < 8; p++) {
        g_bufA[(row0 + p) * Cc + c] = ag[p];
        g_bufB[(row0 + p) * Cc + c] = ah[p];
    }
}

// ---------------------------------------------------------------------------
// K2: depthwise circular conv 5x7x7
// out[b,t,h,w,c] = sum_{kt,kh,kw} K[c,kt,kh,kw] * in[b,(t-kt+2)%16,(h-kh+3)%56,(w-kw+3)%56,c]
// Each thread: fixed (b,t,h,c), 14 consecutive w outputs, sliding window regs.
// grid = (4 w-quarters, H*B*T, 2 tensors), block = 128 (c)
// ---------------------------------------------------------------------------
__global__ void k_conv(void) {
    int c = threadIdx.x;
    int which = blockIdx.z;
    const float* __restrict__ in  = which ? g_bufB : g_bufA;
    float*       __restrict__ out = which ? g_bufD : g_bufC;
    const float* __restrict__ kt_ = g_kT[which];
    int w0  = blockIdx.x * 14;
    int hbt = blockIdx.y;
    int h  = hbt % Hh;
    int bt = hbt / Hh;          // b*16 + t
    int t  = bt & 15;
    int bbase = bt - t;         // b*16
    float acc[14];
    #pragma unroll
    for (int i = 0; i < 14; i++) acc[i] = 0.f;

    for (int ktp = 0; ktp < 5; ktp++) {
        int tin  = (t - ktp + 18) & 15;
        int btin = bbase + tin;
        for (int kh = 0; kh < 7; kh++) {
            int hin = h - kh + 3;
            if (hin < 0)    hin += 56;
            if (hin >= 56)  hin -= 56;
            const float* src = in + ((size_t)(btin * Hh + hin) * Ww) * Cc + c;
            float win[20];
            #pragma unroll
            for (int j = 0; j < 20; j++) {
                int wi = w0 - 3 + j;
                if (wi < 0)   wi += 56;
                if (wi >= 56) wi -= 56;
                win[j] = src[(size_t)wi * Cc];
            }
            const float* kb = kt_ + (ktp * 49 + kh * 7) * Cc + c;
            float kv[7];
            #pragma unroll
            for (int kw = 0; kw < 7; kw++) kv[kw] = kb[kw * Cc];
            #pragma unroll
            for (int i = 0; i < 14; i++) {
                #pragma unroll
                for (int kw = 0; kw < 7; kw++)
                    acc[i] = fmaf(kv[kw], win[i + 6 - kw], acc[i]);
            }
        }
    }
    float* dst = out + ((size_t)(bt * Hh + h) * Ww + w0) * Cc + c;
    #pragma unroll
    for (int i = 0; i < 14; i++) dst[(size_t)i * Cc] = acc[i];
}

// ---------------------------------------------------------------------------
// K3: softplus prep + Heinsen scan over T + exp   (one thread per b,h,w,c)
// ---------------------------------------------------------------------------
__device__ __forceinline__ float softplusf(float x) {
    return fmaxf(x, 0.f) + log1pf(expf(-fabsf(x)));
}
__global__ void k_scan(void) {
    int idx = blockIdx.x * blockDim.x + threadIdx.x;   // B*H*W*C threads
    int c = idx & 127;
    int rest = idx >> 7;
    int w = rest % 56; rest /= 56;
    int h = rest % 56;
    int b = rest / 56;
    size_t base = ((size_t)(b * Tt) * Hh + h) * Ww * Cc + (size_t)w * Cc + c;
    float logh = 0.f;
    for (int t = 0; t < Tt; t++) {
        size_t off = base + (size_t)t * HWC;
        float g  = g_bufC[off];
        float hh = g_bufD[off];
        float lf = -softplusf(g);
        float lv = -softplusf(-g) + logf(hh * hh + 1e-6f);
        if (t == 0) {
            logh = lv;
        } else {
            float u = lf + logh;
            float m = fmaxf(u, lv);
            logh = m + log1pf(expf(fminf(u, lv) - m));
        }
        g_bufA[off] = expf(logh);   // E = exp(log_h)
    }
}

// ---------------------------------------------------------------------------
// K4: ssm = E @ Wo + bo, then LayerNorm over channels -> xn (g_bufB)
// ---------------------------------------------------------------------------
__global__ void k_wo_ln(const float* __restrict__ Wo, const float* __restrict__ bo,
                        const float* __restrict__ lns, const float* __restrict__ lnb) {
    __shared__ float xs[8 * Cc];
    __shared__ float smean[8], srstd[8];
    int c = threadIdx.x;
    size_t row0 = (size_t)blockIdx.x * 8;
    #pragma unroll
    for (int p = 0; p < 8; p++) xs[p * Cc + c] = g_bufA[(row0 + p) * Cc + c];
    __syncthreads();
    float acc[8];
    float bov = bo[c];
    #pragma unroll
    for (int p = 0; p < 8; p++) acc[p] = bov;
    for (int k = 0; k < Cc; k++) {
        float wv = Wo[k * Cc + c];
        #pragma unroll
        for (int p = 0; p < 8; p++) acc[p] = fmaf(xs[p * Cc + k], wv, acc[p]);
    }
    __syncthreads();
    #pragma unroll
    for (int p = 0; p < 8; p++) xs[p * Cc + c] = acc[p];
    __syncthreads();
    // mean/var: 16 threads per row
    int r = c >> 4, l = c & 15;
    float s = 0.f, sq = 0.f;
    #pragma unroll
    for (int j = 0; j < 8; j++) {
        float v = xs[r * Cc + l + 16 * j];
        s += v; sq += v * v;
    }
    #pragma unroll
    for (int off = 8; off; off >>= 1) {
        s  += __shfl_down_sync(0xffffffffu, s,  off, 16);
        sq += __shfl_down_sync(0xffffffffu, sq, off, 16);
    }
    if (l == 0) {
        float mean = s * (1.f / 128.f);
        float var  = sq * (1.f / 128.f) - mean * mean;
        smean[r] = mean;
        srstd[r] = rsqrtf(var + 1e-6f);
    }
    __syncthreads();
    float sc = lns[c], bi = lnb[c];
    #pragma unroll
    for (int p = 0; p < 8; p++) {
        float xn = (acc[p] - smean[p]) * srstd[p] * sc + bi;
        g_bufB[(row0 + p) * Cc + c] = xn;
    }
}

// ---------------------------------------------------------------------------
// K5: MLP (gelu-tanh) + LayerScale + residual -> d_out
// ---------------------------------------------------------------------------
__global__ void k_mlp(const float* __restrict__ x,
                      const float* __restrict__ W1, const float* __restrict__ b1,
                      const float* __restrict__ W2, const float* __restrict__ b2,
                      const float* __restrict__ gamma, float* __restrict__ out) {
    __shared__ float xs[8 * Cc];       // 4 KB
    __shared__ float hsm[8 * HID];     // 16 KB
    int c = threadIdx.x;
    size_t row0 = (size_t)blockIdx.x * 8;
    #pragma unroll
    for (int p = 0; p < 8; p++) xs[p * Cc + c] = g_bufB[(row0 + p) * Cc + c];
    __syncthreads();
    float acc[8][4];
    #pragma unroll
    for (int q = 0; q < 4; q++) {
        float bv = b1[q * Cc + c];
        #pragma unroll
        for (int p = 0; p < 8; p++) acc[p][q] = bv;
    }
    for (int k = 0; k < Cc; k++) {
        float wa = W1[k * HID + c];
        float wb = W1[k * HID + Cc + c];
        float wc = W1[k * HID + 2 * Cc + c];
        float wd = W1[k * HID + 3 * Cc + c];
        #pragma unroll
        for (int p = 0; p < 8; p++) {
            float xv = xs[p * Cc + k];
            acc[p][0] = fmaf(xv, wa, acc[p][0]);
            acc[p][1] = fmaf(xv, wb, acc[p][1]);
            acc[p][2] = fmaf(xv, wc, acc[p][2]);
            acc[p][3] = fmaf(xv, wd, acc[p][3]);
        }
    }
    #pragma unroll
    for (int q = 0; q < 4; q++) {
        #pragma unroll
        for (int p = 0; p < 8; p++) {
            float v = acc[p][q];
            float tg = tanhf(0.7978845608028654f * (v + 0.044715f * v * v * v));
            hsm[p * HID + q * Cc + c] = 0.5f * v * (1.f + tg);
        }
    }
    __syncthreads();
    float oacc[8];
    float b2v = b2[c];
    #pragma unroll
    for (int p = 0; p < 8; p++) oacc[p] = b2v;
    for (int k = 0; k < HID; k++) {
        float wv = W2[k * Cc + c];
        #pragma unroll
        for (int p = 0; p < 8; p++) oacc[p] = fmaf(hsm[p * HID + k], wv, oacc[p]);
    }
    float gv = gamma[c];
    #pragma unroll
    for (int p = 0; p < 8; p++) {
        size_t o = (row0 + p) * Cc + c;
        out[o] = fmaf(oacc[p], gv, x[o]);
    }
}

// ---------------------------------------------------------------------------
extern "C" void kernel_launch(void* const* d_in, const int* in_sizes, int n_in,
                              void* d_out, int out_size) {
    const float* x     = (const float*)d_in[0];
    const float* Wg    = (const float*)d_in[1];
    const float* bg    = (const float*)d_in[2];
    const float* Wh    = (const float*)d_in[3];
    const float* bh    = (const float*)d_in[4];
    const float* gk    = (const float*)d_in[5];
    const float* hk    = (const float*)d_in[6];
    const float* Wo    = (const float*)d_in[7];
    const float* bo    = (const float*)d_in[8];
    const float* lns   = (const float*)d_in[9];
    const float* lnb   = (const float*)d_in[10];
    const float* W1    = (const float*)d_in[11];
    const float* b1    = (const float*)d_in[12];
    const float* W2    = (const float*)d_in[13];
    const float* b2    = (const float*)d_in[14];
    const float* gamma = (const float*)d_in[15];
    float* out = (float*)d_out;

    k_transpose_kernels<<<(2 * Cc * KTAPS + 255) / 256, 256>>>(gk, hk);
    k_proj<<<NPTS / 8, 128>>>(x, Wg, bg, Wh, bh);
    k_conv<<<dim3(4, Hh * Bb * Tt, 2), 128>>>();
    k_scan<<<(Bb * Hh * Ww * Cc) / 256, 256>>>();
    k_wo_ln<<<NPTS / 8, 128>>>(Wo, bo, lns, lnb);
    k_mlp<<<NPTS / 8, 128>>>(x, W1, b1, W2, b2, gamma, out);
}

// round 3
// speedup vs baseline: 2.4664x; 2.4664x over previous
#include <cuda_runtime.h>
#include <cuda_bf16.h>
#include <math.h>
#include <stdint.h>

#define Bb 2
#define Tt 16
#define Hh 56
#define Ww 56
#define Cc 128
#define NPTS (Bb*Tt*Hh*Ww)          /* 100352 */
#define TOT  (NPTS*Cc)              /* 12845056 */
#define HWC  (Hh*Ww*Cc)
#define KTAPS 245
#define NTILES (NPTS/128)           /* 784 */

typedef __nv_bfloat16 bf16;
typedef __nv_bfloat162 bf162;

// ---------------- device scratch (allocation-free) ----------------
__device__ __align__(16) bf16 g_gateP[TOT];
__device__ __align__(16) bf16 g_hidP[TOT];
__device__ __align__(16) bf16 g_gateS[TOT];
__device__ __align__(16) bf16 g_hidS[TOT];
__device__ __align__(16) bf16 g_E[TOT];
__device__ __align__(16) bf16 g_xn[TOT];
__device__ __align__(16) bf16 g_hidden[(size_t)NPTS*512];
__device__ __align__(16) bf16 g_WgT[Cc*Cc];       // [n][k]
__device__ __align__(16) bf16 g_WhT[Cc*Cc];
__device__ __align__(16) bf16 g_WoT[Cc*Cc];
__device__ __align__(16) bf16 g_W1T[512*Cc];      // [n=512][k=128]
__device__ __align__(16) bf16 g_W2T[Cc*512];      // [n=128][k=512]
__device__ __align__(16) bf16 g_kB[2][KTAPS*Cc];  // [tap][c]

// ---------------- helpers ----------------
__device__ __forceinline__ uint32_t smem_u32(const void* p) {
    uint32_t a;
    asm("{ .reg .u64 t; cvta.to.shared.u64 t, %1; cvt.u32.u64 %0, t; }" : "=r"(a) : "l"(p));
    return a;
}
#define LDSM4(r0, r1, r2, r3, a) \
    asm volatile("ldmatrix.sync.aligned.m8n8.x4.shared.b16 {%0,%1,%2,%3}, [%4];" \
        : "=r"(r0), "=r"(r1), "=r"(r2), "=r"(r3) : "r"(a))
#define MMA16816(c, a, b) \
    asm volatile("mma.sync.aligned.m16n8k16.row.col.f32.bf16.bf16.f32 " \
        "{%0,%1,%2,%3},{%4,%5,%6,%7},{%8,%9},{%0,%1,%2,%3};" \
        : "+f"((c)[0]), "+f"((c)[1]), "+f"((c)[2]), "+f"((c)[3]) \
        : "r"((a)[0]), "r"((a)[1]), "r"((a)[2]), "r"((a)[3]), "r"((b)[0]), "r"((b)[1]))

#define SA 136    /* smem row stride (bf16 elems) for 128-col tiles */
#define SA2 264   /* stride for 256-col tiles */

// ---------------------------------------------------------------------------
// K0: weight prep — transposed bf16 copies of all weights + conv kernels
// ---------------------------------------------------------------------------
__global__ void k_prep(const float* __restrict__ Wg, const float* __restrict__ Wh,
                       const float* __restrict__ Wo, const float* __restrict__ W1,
                       const float* __restrict__ W2, const float* __restrict__ gk,
                       const float* __restrict__ hk) {
    int i = blockIdx.x * 256 + threadIdx.x;
    if (i < 16384) {
        int n = i >> 7, k = i & 127;
        g_WgT[i] = __float2bfloat16(Wg[k * 128 + n]);
        g_WhT[i] = __float2bfloat16(Wh[k * 128 + n]);
        g_WoT[i] = __float2bfloat16(Wo[k * 128 + n]);
    }
    if (i < 65536) {
        int n = i >> 7, k = i & 127;
        g_W1T[i] = __float2bfloat16(W1[k * 512 + n]);
        int n2 = i >> 9, k2 = i & 511;
        g_W2T[i] = __float2bfloat16(W2[k2 * 128 + n2]);
    }
    if (i < 2 * KTAPS * 128) {
        int which = i / (KTAPS * 128);
        int j = i - which * (KTAPS * 128);
        int tap = j >> 7, c = j & 127;
        const float* s = which ? hk : gk;
        g_kB[which][j] = __float2bfloat16(s[c * KTAPS + tap]);
    }
}

// ---------------------------------------------------------------------------
// K1: dual projection  [128,128] x (Wg | Wh) -> g_gateP, g_hidP (bf16)
// 4 warps: warps 0,1 -> gate n[0:64),[64:128); warps 2,3 -> hidden
// ---------------------------------------------------------------------------
#define PROJ_SMEM (3*128*SA*2 + 256*4)
__global__ void __launch_bounds__(128) k_proj(const float* __restrict__ x,
                                              const float* __restrict__ bg,
                                              const float* __restrict__ bh) {
    extern __shared__ __align__(16) char sm[];
    bf16* As = (bf16*)sm;                       // 128 x SA
    bf16* Bs = As + 128 * SA;                   // 2 x (128 x SA)
    float* sbias = (float*)(Bs + 2 * 128 * SA); // 256 floats
    int tid = threadIdx.x, w = tid >> 5, l = tid & 31;
    size_t m0 = (size_t)blockIdx.x * 128;
    sbias[tid] = bg[tid];
    sbias[128 + tid] = bh[tid];

    const float2* xs = (const float2*)(x + m0 * 128);
    for (int idx = tid; idx < 128 * 64; idx += 128) {
        int r = idx >> 6, cp = idx & 63;
        float2 v = xs[idx];
        *(bf162*)(As + r * SA + cp * 2) = __floats2bfloat162_rn(v.x, v.y);
    }
    const uint4* wgp = (const uint4*)g_WgT;
    const uint4* whp = (const uint4*)g_WhT;
    for (int idx = tid; idx < 128 * 16; idx += 128) {
        int r = idx >> 4, c = idx & 15;
        *(uint4*)(Bs + r * SA + c * 8) = wgp[idx];
        *(uint4*)(Bs + 128 * SA + r * SA + c * 8) = whp[idx];
    }
    __syncthreads();

    int which = w >> 1;
    int wn0 = (w & 1) * 64;
    uint32_t Abase = smem_u32(As) + ((l & 15) * SA + (l >> 4) * 8) * 2;
    uint32_t Bbase = smem_u32(Bs + which * 128 * SA) + ((l & 15) * SA + (l >> 4) * 8) * 2 + wn0 * SA * 2;
    bf16* outb = which ? g_hidP : g_gateP;
    float* bb = sbias + which * 128;
    int quad = l >> 2, t4 = l & 3;

    for (int mc = 0; mc < 4; mc++) {
        float acc[2][8][4];
        #pragma unroll
        for (int mf = 0; mf < 2; mf++)
            #pragma unroll
            for (int nf = 0; nf < 8; nf++)
                #pragma unroll
                for (int e = 0; e < 4; e++) acc[mf][nf][e] = 0.f;
        #pragma unroll
        for (int k = 0; k < 8; k++) {
            uint32_t a[2][4], b[8][2];
            #pragma unroll
            for (int mf = 0; mf < 2; mf++)
                LDSM4(a[mf][0], a[mf][1], a[mf][2], a[mf][3],
                      Abase + (mc * 32 + mf * 16) * SA * 2 + k * 32);
            #pragma unroll
            for (int nf2 = 0; nf2 < 4; nf2++) {
                uint32_t r0, r1, r2, r3;
                LDSM4(r0, r1, r2, r3, Bbase + nf2 * 16 * SA * 2 + k * 32);
                b[nf2 * 2][0] = r0; b[nf2 * 2][1] = r2;
                b[nf2 * 2 + 1][0] = r1; b[nf2 * 2 + 1][1] = r3;
            }
            #pragma unroll
            for (int mf = 0; mf < 2; mf++)
                #pragma unroll
                for (int nf = 0; nf < 8; nf++) MMA16816(acc[mf][nf], a[mf], b[nf]);
        }
        #pragma unroll
        for (int mf = 0; mf < 2; mf++)
            #pragma unroll
            for (int nf = 0; nf < 8; nf++) {
                int n = wn0 + nf * 8 + t4 * 2;
                int r0 = mc * 32 + mf * 16 + quad;
                *(bf162*)(outb + (m0 + r0) * 128 + n) =
                    __floats2bfloat162_rn(acc[mf][nf][0] + bb[n], acc[mf][nf][1] + bb[n + 1]);
                *(bf162*)(outb + (m0 + r0 + 8) * 128 + n) =
                    __floats2bfloat162_rn(acc[mf][nf][2] + bb[n], acc[mf][nf][3] + bb[n + 1]);
            }
    }
}

// ---------------------------------------------------------------------------
// K2: depthwise circular conv 5x7x7, bf16 HFMA2.
// block (32 ch-threads x 4 w-quarters); thread = 4 channels (2 bf162)
// ---------------------------------------------------------------------------
__global__ void __launch_bounds__(128) k_conv(void) {
    int ct = threadIdx.x;           // 0..31 -> channels 4*ct..4*ct+3
    int wq = threadIdx.y;           // 0..3
    int which = blockIdx.z;
    const uint2* __restrict__ in = (const uint2*)(which ? g_hidP : g_gateP);
    uint2* __restrict__ outp = (uint2*)(which ? g_hidS : g_gateS);
    const uint2* __restrict__ kt = (const uint2*)g_kB[which];
    int w0 = wq * 14;
    int hbt = blockIdx.x;
    int h = hbt % Hh;
    int bt = hbt / Hh;
    int t = bt & 15;
    int bbase = bt - t;

    bf162 acc[14][2];
    bf162 z = __floats2bfloat162_rn(0.f, 0.f);
    #pragma unroll
    for (int i = 0; i < 14; i++) { acc[i][0] = z; acc[i][1] = z; }

    for (int ktp = 0; ktp < 5; ktp++) {
        int tin = (t - ktp + 18) & 15;
        int btin = bbase + tin;
        for (int kh = 0; kh < 7; kh++) {
            int hin = h - kh + 3;
            if (hin < 0)   hin += 56;
            if (hin >= 56) hin -= 56;
            const uint2* src = in + (size_t)(btin * Hh + hin) * (Ww * 32) + ct;
            uint2 win[20];
            #pragma unroll
            for (int j = 0; j < 20; j++) {
                int wi = w0 - 3 + j;
                if (wi < 0)   wi += 56;
                if (wi >= 56) wi -= 56;
                win[j] = src[(size_t)wi * 32];
            }
            const uint2* kb = kt + (size_t)(ktp * 49 + kh * 7) * 32 + ct;
            uint2 kv[7];
            #pragma unroll
            for (int kw = 0; kw < 7; kw++) kv[kw] = kb[(size_t)kw * 32];
            #pragma unroll
            for (int i = 0; i < 14; i++) {
                #pragma unroll
                for (int kw = 0; kw < 7; kw++) {
                    bf162 klo = *(bf162*)&kv[kw].x;
                    bf162 khi = *(bf162*)&kv[kw].y;
                    bf162 wlo = *(bf162*)&win[i + 6 - kw].x;
                    bf162 whi = *(bf162*)&win[i + 6 - kw].y;
                    acc[i][0] = __hfma2(klo, wlo, acc[i][0]);
                    acc[i][1] = __hfma2(khi, whi, acc[i][1]);
                }
            }
        }
    }
    uint2* dst = outp + ((size_t)(bt * Hh + h) * Ww + w0) * 32 + ct;
    #pragma unroll
    for (int i = 0; i < 14; i++) {
        uint2 v;
        v.x = *(uint32_t*)&acc[i][0];
        v.y = *(uint32_t*)&acc[i][1];
        dst[(size_t)i * 32] = v;
    }
}

// ---------------------------------------------------------------------------
// K3: softplus prep + Heinsen scan over T + exp -> g_E (bf16)
// ---------------------------------------------------------------------------
__device__ __forceinline__ float softplusf(float x) {
    return fmaxf(x, 0.f) + log1pf(expf(-fabsf(x)));
}
__global__ void k_scan(void) {
    int idx = blockIdx.x * 256 + threadIdx.x;
    int c = idx & 127;
    int rest = idx >> 7;
    int w = rest % 56; rest /= 56;
    int h = rest % 56;
    int b = rest / 56;
    size_t base = ((size_t)(b * Tt) * Hh + h) * Ww * Cc + (size_t)w * Cc + c;
    float logh = 0.f;
    for (int t = 0; t < Tt; t++) {
        size_t off = base + (size_t)t * HWC;
        float g = __bfloat162float(g_gateS[off]);
        float hh = __bfloat162float(g_hidS[off]);
        float lf = -softplusf(g);
        float lv = -softplusf(-g) + logf(hh * hh + 1e-6f);
        if (t == 0) logh = lv;
        else {
            float u = lf + logh;
            float m = fmaxf(u, lv);
            logh = m + log1pf(expf(fminf(u, lv) - m));
        }
        g_E[off] = __float2bfloat16(expf(logh));
    }
}

// ---------------------------------------------------------------------------
// K4: ssm = E @ Wo + bo -> LayerNorm -> g_xn (bf16). 4 warps, n=32 each.
// ---------------------------------------------------------------------------
#define WO_SMEM (2*128*SA*2 + 128*129*4 + 3*128*4)
__global__ void __launch_bounds__(128) k_wo(const float* __restrict__ bo,
                                            const float* __restrict__ lns,
                                            const float* __restrict__ lnb) {
    extern __shared__ __align__(16) char sm[];
    bf16* As = (bf16*)sm;
    bf16* Bs = As + 128 * SA;
    float* stg = (float*)(Bs + 128 * SA);       // 128 x 129
    float* sbo = stg + 128 * 129;
    float* slns = sbo + 128;
    float* slnb = slns + 128;
    int tid = threadIdx.x, w = tid >> 5, l = tid & 31;
    size_t m0 = (size_t)blockIdx.x * 128;
    sbo[tid] = bo[tid]; slns[tid] = lns[tid]; slnb[tid] = lnb[tid];

    const uint4* ep = (const uint4*)(g_E + m0 * 128);
    const uint4* wop = (const uint4*)g_WoT;
    for (int idx = tid; idx < 128 * 16; idx += 128) {
        int r = idx >> 4, c = idx & 15;
        *(uint4*)(As + r * SA + c * 8) = ep[idx];
        *(uint4*)(Bs + r * SA + c * 8) = wop[idx];
    }
    __syncthreads();

    int wn0 = w * 32;
    uint32_t Abase = smem_u32(As) + ((l & 15) * SA + (l >> 4) * 8) * 2;
    uint32_t Bbase = smem_u32(Bs) + ((l & 15) * SA + (l >> 4) * 8) * 2 + wn0 * SA * 2;
    int quad = l >> 2, t4 = l & 3;

    for (int mc = 0; mc < 4; mc++) {
        float acc[2][4][4];
        #pragma unroll
        for (int mf = 0; mf < 2; mf++)
            #pragma unroll
            for (int nf = 0; nf < 4; nf++)
                #pragma unroll
                for (int e = 0; e < 4; e++) acc[mf][nf][e] = 0.f;
        #pragma unroll
        for (int k = 0; k < 8; k++) {
            uint32_t a[2][4], b[4][2];
            #pragma unroll
            for (int mf = 0; mf < 2; mf++)
                LDSM4(a[mf][0], a[mf][1], a[mf][2], a[mf][3],
                      Abase + (mc * 32 + mf * 16) * SA * 2 + k * 32);
            #pragma unroll
            for (int nf2 = 0; nf2 < 2; nf2++) {
                uint32_t r0, r1, r2, r3;
                LDSM4(r0, r1, r2, r3, Bbase + nf2 * 16 * SA * 2 + k * 32);
                b[nf2 * 2][0] = r0; b[nf2 * 2][1] = r2;
                b[nf2 * 2 + 1][0] = r1; b[nf2 * 2 + 1][1] = r3;
            }
            #pragma unroll
            for (int mf = 0; mf < 2; mf++)
                #pragma unroll
                for (int nf = 0; nf < 4; nf++) MMA16816(acc[mf][nf], a[mf], b[nf]);
        }
        #pragma unroll
        for (int mf = 0; mf < 2; mf++)
            #pragma unroll
            for (int nf = 0; nf < 4; nf++) {
                int n = wn0 + nf * 8 + t4 * 2;
                int r0 = mc * 32 + mf * 16 + quad;
                stg[r0 * 129 + n] = acc[mf][nf][0] + sbo[n];
                stg[r0 * 129 + n + 1] = acc[mf][nf][1] + sbo[n + 1];
                stg[(r0 + 8) * 129 + n] = acc[mf][nf][2] + sbo[n];
                stg[(r0 + 8) * 129 + n + 1] = acc[mf][nf][3] + sbo[n + 1];
            }
    }
    __syncthreads();
    // LayerNorm: thread tid owns row tid
    float sum = 0.f, sq = 0.f;
    #pragma unroll 8
    for (int c = 0; c < 128; c++) {
        float v = stg[tid * 129 + c];
        sum += v; sq += v * v;
    }
    float mean = sum * (1.f / 128.f);
    float var = sq * (1.f / 128.f) - mean * mean;
    float rstd = rsqrtf(var + 1e-6f);
    bf162* dst = (bf162*)(g_xn + (m0 + tid) * 128);
    #pragma unroll 8
    for (int cp = 0; cp < 64; cp++) {
        int c = cp * 2;
        float a = (stg[tid * 129 + c] - mean) * rstd * slns[c] + slnb[c];
        float b = (stg[tid * 129 + c + 1] - mean) * rstd * slns[c + 1] + slnb[c + 1];
        dst[cp] = __floats2bfloat162_rn(a, b);
    }
}

// ---------------------------------------------------------------------------
// K5: MLP1  xn[128,128] @ W1 -> gelu -> g_hidden (bf16). 8 warps, n=64 each.
// ---------------------------------------------------------------------------
#define M1_SMEM (128*SA*2 + 512*SA*2 + 512*4)
__global__ void __launch_bounds__(256) k_mlp1(const float* __restrict__ b1) {
    extern __shared__ __align__(16) char sm[];
    bf16* As = (bf16*)sm;
    bf16* Bs = As + 128 * SA;
    float* sb1 = (float*)(Bs + 512 * SA);
    int tid = threadIdx.x, w = tid >> 5, l = tid & 31;
    size_t m0 = (size_t)blockIdx.x * 128;
    sb1[tid] = b1[tid]; sb1[256 + tid] = b1[256 + tid];

    const uint4* xp = (const uint4*)(g_xn + m0 * 128);
    for (int idx = tid; idx < 128 * 16; idx += 256) {
        int r = idx >> 4, c = idx & 15;
        *(uint4*)(As + r * SA + c * 8) = xp[idx];
    }
    const uint4* w1p = (const uint4*)g_W1T;
    for (int idx = tid; idx < 512 * 16; idx += 256) {
        int r = idx >> 4, c = idx & 15;
        *(uint4*)(Bs + r * SA + c * 8) = w1p[idx];
    }
    __syncthreads();

    int wn0 = w * 64;
    uint32_t Abase = smem_u32(As) + ((l & 15) * SA + (l >> 4) * 8) * 2;
    uint32_t Bbase = smem_u32(Bs) + ((l & 15) * SA + (l >> 4) * 8) * 2 + wn0 * SA * 2;
    int quad = l >> 2, t4 = l & 3;

    for (int mc = 0; mc < 4; mc++) {
        float acc[2][8][4];
        #pragma unroll
        for (int mf = 0; mf < 2; mf++)
            #pragma unroll
            for (int nf = 0; nf < 8; nf++)
                #pragma unroll
                for (int e = 0; e < 4; e++) acc[mf][nf][e] = 0.f;
        #pragma unroll
        for (int k = 0; k < 8; k++) {
            uint32_t a[2][4], b[8][2];
            #pragma unroll
            for (int mf = 0; mf < 2; mf++)
                LDSM4(a[mf][0], a[mf][1], a[mf][2], a[mf][3],
                      Abase + (mc * 32 + mf * 16) * SA * 2 + k * 32);
            #pragma unroll
            for (int nf2 = 0; nf2 < 4; nf2++) {
                uint32_t r0, r1, r2, r3;
                LDSM4(r0, r1, r2, r3, Bbase + nf2 * 16 * SA * 2 + k * 32);
                b[nf2 * 2][0] = r0; b[nf2 * 2][1] = r2;
                b[nf2 * 2 + 1][0] = r1; b[nf2 * 2 + 1][1] = r3;
            }
            #pragma unroll
            for (int mf = 0; mf < 2; mf++)
                #pragma unroll
                for (int nf = 0; nf < 8; nf++) MMA16816(acc[mf][nf], a[mf], b[nf]);
        }
        #pragma unroll
        for (int mf = 0; mf < 2; mf++)
            #pragma unroll
            for (int nf = 0; nf < 8; nf++) {
                int n = wn0 + nf * 8 + t4 * 2;
                int r0 = mc * 32 + mf * 16 + quad;
                #pragma unroll
                for (int hrow = 0; hrow < 2; hrow++) {
                    float v0 = acc[mf][nf][hrow * 2] + sb1[n];
                    float v1 = acc[mf][nf][hrow * 2 + 1] + sb1[n + 1];
                    float t0 = tanhf(0.7978845608028654f * (v0 + 0.044715f * v0 * v0 * v0));
                    float t1 = tanhf(0.7978845608028654f * (v1 + 0.044715f * v1 * v1 * v1));
                    *(bf162*)(g_hidden + (m0 + r0 + hrow * 8) * 512 + n) =
                        __floats2bfloat162_rn(0.5f * v0 * (1.f + t0), 0.5f * v1 * (1.f + t1));
                }
            }
    }
}

// ---------------------------------------------------------------------------
// K6: MLP2  hidden[128,512] @ W2 (K split 2x256) + gamma*.. + x -> out (f32)
// 8 warps, n=16 each. Acc held across phases.
// ---------------------------------------------------------------------------
#define M2_SMEM (2*128*SA2*2 + 256*4)
__global__ void __launch_bounds__(256) k_mlp2(const float* __restrict__ x,
                                              const float* __restrict__ b2,
                                              const float* __restrict__ gamma,
                                              float* __restrict__ out) {
    extern __shared__ __align__(16) char sm[];
    bf16* As = (bf16*)sm;
    bf16* Bs = As + 128 * SA2;
    float* sb2 = (float*)(Bs + 128 * SA2);
    float* sgm = sb2 + 128;
    int tid = threadIdx.x, w = tid >> 5, l = tid & 31;
    size_t m0 = (size_t)blockIdx.x * 128;
    if (tid < 128) { sb2[tid] = b2[tid]; sgm[tid] = gamma[tid]; }

    int wn0 = w * 16;
    uint32_t Ab = smem_u32(As) + ((l & 15) * SA2 + (l >> 4) * 8) * 2;
    uint32_t Bb_ = smem_u32(Bs) + ((l & 15) * SA2 + (l >> 4) * 8) * 2 + wn0 * SA2 * 2;
    int quad = l >> 2, t4 = l & 3;

    float acc[4][2][2][4];
    #pragma unroll
    for (int mc = 0; mc < 4; mc++)
        #pragma unroll
        for (int mf = 0; mf < 2; mf++)
            #pragma unroll
            for (int nf = 0; nf < 2; nf++)
                #pragma unroll
                for (int e = 0; e < 4; e++) acc[mc][mf][nf][e] = 0.f;

    const uint4* hp = (const uint4*)g_hidden;
    const uint4* w2p = (const uint4*)g_W2T;
    for (int ph = 0; ph < 2; ph++) {
        if (ph) __syncthreads();
        for (int idx = tid; idx < 128 * 32; idx += 256) {
            int r = idx >> 5, c = idx & 31;
            *(uint4*)(As + r * SA2 + c * 8) = hp[(m0 + r) * 64 + ph * 32 + c];
            *(uint4*)(Bs + r * SA2 + c * 8) = w2p[(size_t)r * 64 + ph * 32 + c];
        }
        __syncthreads();
        for (int mc = 0; mc < 4; mc++) {
            #pragma unroll
            for (int k = 0; k < 16; k++) {
                uint32_t a[2][4], b[2][2];
                #pragma unroll
                for (int mf = 0; mf < 2; mf++)
                    LDSM4(a[mf][0], a[mf][1], a[mf][2], a[mf][3],
                          Ab + (mc * 32 + mf * 16) * SA2 * 2 + k * 32);
                uint32_t r0, r1, r2, r3;
                LDSM4(r0, r1, r2, r3, Bb_ + k * 32);
                b[0][0] = r0; b[0][1] = r2;
                b[1][0] = r1; b[1][1] = r3;
                #pragma unroll
                for (int mf = 0; mf < 2; mf++)
                    #pragma unroll
                    for (int nf = 0; nf < 2; nf++) MMA16816(acc[mc][mf][nf], a[mf], b[nf]);
            }
        }
    }
    #pragma unroll
    for (int mc = 0; mc < 4; mc++)
        #pragma unroll
        for (int mf = 0; mf < 2; mf++)
            #pragma unroll
            for (int nf = 0; nf < 2; nf++) {
                int n = wn0 + nf * 8 + t4 * 2;
                size_t r0 = m0 + mc * 32 + mf * 16 + quad;
                #pragma unroll
                for (int hrow = 0; hrow < 2; hrow++) {
                    size_t r = r0 + hrow * 8;
                    float v0 = (acc[mc][mf][nf][hrow * 2] + sb2[n]) * sgm[n] + x[r * 128 + n];
                    float v1 = (acc[mc][mf][nf][hrow * 2 + 1] + sb2[n + 1]) * sgm[n + 1] + x[r * 128 + n + 1];
                    out[r * 128 + n] = v0;
                    out[r * 128 + n + 1] = v1;
                }
            }
}

// ---------------------------------------------------------------------------
extern "C" void kernel_launch(void* const* d_in, const int* in_sizes, int n_in,
                              void* d_out, int out_size) {
    const float* x     = (const float*)d_in[0];
    const float* Wg    = (const float*)d_in[1];
    const float* bg    = (const float*)d_in[2];
    const float* Wh    = (const float*)d_in[3];
    const float* bh    = (const float*)d_in[4];
    const float* gk    = (const float*)d_in[5];
    const float* hk    = (const float*)d_in[6];
    const float* Wo    = (const float*)d_in[7];
    const float* bo    = (const float*)d_in[8];
    const float* lns   = (const float*)d_in[9];
    const float* lnb   = (const float*)d_in[10];
    const float* W1    = (const float*)d_in[11];
    const float* b1    = (const float*)d_in[12];
    const float* W2    = (const float*)d_in[13];
    const float* b2    = (const float*)d_in[14];
    const float* gamma = (const float*)d_in[15];
    float* out = (float*)d_out;

    cudaFuncSetAttribute(k_proj, cudaFuncAttributeMaxDynamicSharedMemorySize, PROJ_SMEM);
    cudaFuncSetAttribute(k_wo,   cudaFuncAttributeMaxDynamicSharedMemorySize, WO_SMEM);
    cudaFuncSetAttribute(k_mlp1, cudaFuncAttributeMaxDynamicSharedMemorySize, M1_SMEM);
    cudaFuncSetAttribute(k_mlp2, cudaFuncAttributeMaxDynamicSharedMemorySize, M2_SMEM);

    k_prep<<<256, 256>>>(Wg, Wh, Wo, W1, W2, gk, hk);
    k_proj<<<NTILES, 128, PROJ_SMEM>>>(x, bg, bh);
    k_conv<<<dim3(Hh * Bb * Tt, 1, 2), dim3(32, 4)>>>();
    k_scan<<<(Bb * Hh * Ww * Cc) / 256, 256>>>();
    k_wo<<<NTILES, 128, WO_SMEM>>>(bo, lns, lnb);
    k_mlp1<<<NTILES, 256, M1_SMEM>>>(b1);
    k_mlp2<<<NTILES, 256, M2_SMEM>>>(x, b2, gamma, out);
}

// round 4
// speedup vs baseline: 2.6995x; 1.0945x over previous
#include <cuda_runtime.h>
#include <cuda_bf16.h>
#include <math.h>
#include <stdint.h>

#define Bb 2
#define Tt 16
#define Hh 56
#define Ww 56
#define Cc 128
#define NPTS (Bb*Tt*Hh*Ww)          /* 100352 */
#define TOT  (NPTS*Cc)              /* 12845056 */
#define HWC  (Hh*Ww*Cc)
#define KTAPS 245
#define NTILES (NPTS/128)           /* 784 */

typedef __nv_bfloat16 bf16;
typedef __nv_bfloat162 bf162;

// ---------------- device scratch (allocation-free) ----------------
__device__ __align__(16) bf16 g_gateP[TOT];
__device__ __align__(16) bf16 g_hidP[TOT];
__device__ __align__(16) bf16 g_gateS[TOT];
__device__ __align__(16) bf16 g_hidS[TOT];
__device__ __align__(16) bf16 g_E[TOT];
__device__ __align__(16) bf16 g_xn[TOT];
__device__ __align__(16) bf16 g_hidden[(size_t)NPTS*512];
__device__ __align__(16) bf16 g_WgT[Cc*Cc];       // [n][k]
__device__ __align__(16) bf16 g_WhT[Cc*Cc];
__device__ __align__(16) bf16 g_WoT[Cc*Cc];
__device__ __align__(16) bf16 g_W1T[512*Cc];      // [n=512][k=128]
__device__ __align__(16) bf16 g_W2T[Cc*512];      // [n=128][k=512]
__device__ __align__(16) bf16 g_kB[2][KTAPS*Cc];  // [tap][c]

// ---------------- helpers ----------------
__device__ __forceinline__ uint32_t smem_u32(const void* p) {
    uint32_t a;
    asm("{ .reg .u64 t; cvta.to.shared.u64 t, %1; cvt.u32.u64 %0, t; }" : "=r"(a) : "l"(p));
    return a;
}
#define LDSM4(r0, r1, r2, r3, a) \
    asm volatile("ldmatrix.sync.aligned.m8n8.x4.shared.b16 {%0,%1,%2,%3}, [%4];" \
        : "=r"(r0), "=r"(r1), "=r"(r2), "=r"(r3) : "r"(a))
#define MMA16816(c, a, b) \
    asm volatile("mma.sync.aligned.m16n8k16.row.col.f32.bf16.bf16.f32 " \
        "{%0,%1,%2,%3},{%4,%5,%6,%7},{%8,%9},{%0,%1,%2,%3};" \
        : "+f"((c)[0]), "+f"((c)[1]), "+f"((c)[2]), "+f"((c)[3]) \
        : "r"((a)[0]), "r"((a)[1]), "r"((a)[2]), "r"((a)[3]), "r"((b)[0]), "r"((b)[1]))

__device__ __forceinline__ float tanh_fast(float x) {
    float y;
    asm("tanh.approx.f32 %0, %1;" : "=f"(y) : "f"(x));
    return y;
}
__device__ __forceinline__ float exp_fast(float x) {
    float y;
    asm("ex2.approx.f32 %0, %1;" : "=f"(y) : "f"(x * 1.4426950408889634f));
    return y;
}
__device__ __forceinline__ float rcp_fast(float x) {
    float y;
    asm("rcp.approx.f32 %0, %1;" : "=f"(y) : "f"(x));
    return y;
}

#define SA 136    /* smem row stride (bf16 elems) for 128-col tiles */
#define SA2 264   /* stride for 256-col tiles */

// ---------------------------------------------------------------------------
// K0: weight prep — transposed bf16 copies of all weights + conv kernels
// ---------------------------------------------------------------------------
__global__ void k_prep(const float* __restrict__ Wg, const float* __restrict__ Wh,
                       const float* __restrict__ Wo, const float* __restrict__ W1,
                       const float* __restrict__ W2, const float* __restrict__ gk,
                       const float* __restrict__ hk) {
    int i = blockIdx.x * 256 + threadIdx.x;
    if (i < 16384) {
        int n = i >> 7, k = i & 127;
        g_WgT[i] = __float2bfloat16(Wg[k * 128 + n]);
        g_WhT[i] = __float2bfloat16(Wh[k * 128 + n]);
        g_WoT[i] = __float2bfloat16(Wo[k * 128 + n]);
    }
    if (i < 65536) {
        int n = i >> 7, k = i & 127;
        g_W1T[i] = __float2bfloat16(W1[k * 512 + n]);
        int n2 = i >> 9, k2 = i & 511;
        g_W2T[i] = __float2bfloat16(W2[k2 * 128 + n2]);
    }
    if (i < 2 * KTAPS * 128) {
        int which = i / (KTAPS * 128);
        int j = i - which * (KTAPS * 128);
        int tap = j >> 7, c = j & 127;
        const float* s = which ? hk : gk;
        g_kB[which][j] = __float2bfloat16(s[c * KTAPS + tap]);
    }
}

// ---------------------------------------------------------------------------
// K1: dual projection  [128,128] x (Wg | Wh) -> g_gateP, g_hidP (bf16)
// ---------------------------------------------------------------------------
#define PROJ_SMEM (3*128*SA*2 + 256*4)
__global__ void __launch_bounds__(128) k_proj(const float* __restrict__ x,
                                              const float* __restrict__ bg,
                                              const float* __restrict__ bh) {
    extern __shared__ __align__(16) char sm[];
    bf16* As = (bf16*)sm;                       // 128 x SA
    bf16* Bs = As + 128 * SA;                   // 2 x (128 x SA)
    float* sbias = (float*)(Bs + 2 * 128 * SA); // 256 floats
    int tid = threadIdx.x, w = tid >> 5, l = tid & 31;
    size_t m0 = (size_t)blockIdx.x * 128;
    sbias[tid] = bg[tid];
    sbias[128 + tid] = bh[tid];

    const float2* xs = (const float2*)(x + m0 * 128);
    for (int idx = tid; idx < 128 * 64; idx += 128) {
        int r = idx >> 6, cp = idx & 63;
        float2 v = xs[idx];
        *(bf162*)(As + r * SA + cp * 2) = __floats2bfloat162_rn(v.x, v.y);
    }
    const uint4* wgp = (const uint4*)g_WgT;
    const uint4* whp = (const uint4*)g_WhT;
    for (int idx = tid; idx < 128 * 16; idx += 128) {
        int r = idx >> 4, c = idx & 15;
        *(uint4*)(Bs + r * SA + c * 8) = wgp[idx];
        *(uint4*)(Bs + 128 * SA + r * SA + c * 8) = whp[idx];
    }
    __syncthreads();

    int which = w >> 1;
    int wn0 = (w & 1) * 64;
    uint32_t Abase = smem_u32(As) + ((l & 15) * SA + (l >> 4) * 8) * 2;
    uint32_t Bbase = smem_u32(Bs + which * 128 * SA) + ((l & 15) * SA + (l >> 4) * 8) * 2 + wn0 * SA * 2;
    bf16* outb = which ? g_hidP : g_gateP;
    float* bb = sbias + which * 128;
    int quad = l >> 2, t4 = l & 3;

    for (int mc = 0; mc < 4; mc++) {
        float acc[2][8][4];
        #pragma unroll
        for (int mf = 0; mf < 2; mf++)
            #pragma unroll
            for (int nf = 0; nf < 8; nf++)
                #pragma unroll
                for (int e = 0; e < 4; e++) acc[mf][nf][e] = 0.f;
        #pragma unroll
        for (int k = 0; k < 8; k++) {
            uint32_t a[2][4], b[8][2];
            #pragma unroll
            for (int mf = 0; mf < 2; mf++)
                LDSM4(a[mf][0], a[mf][1], a[mf][2], a[mf][3],
                      Abase + (mc * 32 + mf * 16) * SA * 2 + k * 32);
            #pragma unroll
            for (int nf2 = 0; nf2 < 4; nf2++) {
                uint32_t r0, r1, r2, r3;
                LDSM4(r0, r1, r2, r3, Bbase + nf2 * 16 * SA * 2 + k * 32);
                b[nf2 * 2][0] = r0; b[nf2 * 2][1] = r2;
                b[nf2 * 2 + 1][0] = r1; b[nf2 * 2 + 1][1] = r3;
            }
            #pragma unroll
            for (int mf = 0; mf < 2; mf++)
                #pragma unroll
                for (int nf = 0; nf < 8; nf++) MMA16816(acc[mf][nf], a[mf], b[nf]);
        }
        #pragma unroll
        for (int mf = 0; mf < 2; mf++)
            #pragma unroll
            for (int nf = 0; nf < 8; nf++) {
                int n = wn0 + nf * 8 + t4 * 2;
                int r0 = mc * 32 + mf * 16 + quad;
                *(bf162*)(outb + (m0 + r0) * 128 + n) =
                    __floats2bfloat162_rn(acc[mf][nf][0] + bb[n], acc[mf][nf][1] + bb[n + 1]);
                *(bf162*)(outb + (m0 + r0 + 8) * 128 + n) =
                    __floats2bfloat162_rn(acc[mf][nf][2] + bb[n], acc[mf][nf][3] + bb[n + 1]);
            }
    }
}

// ---------------------------------------------------------------------------
// K2: depthwise circular conv 5x7x7, bf16 HFMA2 (unchanged from round 3)
// ---------------------------------------------------------------------------
__global__ void __launch_bounds__(128) k_conv(void) {
    int ct = threadIdx.x;
    int wq = threadIdx.y;
    int which = blockIdx.z;
    const uint2* __restrict__ in = (const uint2*)(which ? g_hidP : g_gateP);
    uint2* __restrict__ outp = (uint2*)(which ? g_hidS : g_gateS);
    const uint2* __restrict__ kt = (const uint2*)g_kB[which];
    int w0 = wq * 14;
    int hbt = blockIdx.x;
    int h = hbt % Hh;
    int bt = hbt / Hh;
    int t = bt & 15;
    int bbase = bt - t;

    bf162 acc[14][2];
    bf162 z = __floats2bfloat162_rn(0.f, 0.f);
    #pragma unroll
    for (int i = 0; i < 14; i++) { acc[i][0] = z; acc[i][1] = z; }

    for (int ktp = 0; ktp < 5; ktp++) {
        int tin = (t - ktp + 18) & 15;
        int btin = bbase + tin;
        for (int kh = 0; kh < 7; kh++) {
            int hin = h - kh + 3;
            if (hin < 0)   hin += 56;
            if (hin >= 56) hin -= 56;
            const uint2* src = in + (size_t)(btin * Hh + hin) * (Ww * 32) + ct;
            uint2 win[20];
            #pragma unroll
            for (int j = 0; j < 20; j++) {
                int wi = w0 - 3 + j;
                if (wi < 0)   wi += 56;
                if (wi >= 56) wi -= 56;
                win[j] = src[(size_t)wi * 32];
            }
            const uint2* kb = kt + (size_t)(ktp * 49 + kh * 7) * 32 + ct;
            uint2 kv[7];
            #pragma unroll
            for (int kw = 0; kw < 7; kw++) kv[kw] = kb[(size_t)kw * 32];
            #pragma unroll
            for (int i = 0; i < 14; i++) {
                #pragma unroll
                for (int kw = 0; kw < 7; kw++) {
                    bf162 klo = *(bf162*)&kv[kw].x;
                    bf162 khi = *(bf162*)&kv[kw].y;
                    bf162 wlo = *(bf162*)&win[i + 6 - kw].x;
                    bf162 whi = *(bf162*)&win[i + 6 - kw].y;
                    acc[i][0] = __hfma2(klo, wlo, acc[i][0]);
                    acc[i][1] = __hfma2(khi, whi, acc[i][1]);
                }
            }
        }
    }
    uint2* dst = outp + ((size_t)(bt * Hh + h) * Ww + w0) * 32 + ct;
    #pragma unroll
    for (int i = 0; i < 14; i++) {
        uint2 v;
        v.x = *(uint32_t*)&acc[i][0];
        v.y = *(uint32_t*)&acc[i][1];
        dst[(size_t)i * 32] = v;
    }
}

// ---------------------------------------------------------------------------
// K3: LINEAR-domain Heinsen scan:  H_t = sigmoid(-g)*H_{t-1} + sigmoid(g)*(h^2+1e-6)
// One thread per 2 channels (bf162), 16 sequential t-steps.
// ---------------------------------------------------------------------------
__global__ void k_scan(void) {
    int idx = blockIdx.x * 256 + threadIdx.x;   // over B*H*W*64 channel-pairs
    int cp = idx & 63;
    int rest = idx >> 6;
    int w = rest % 56; rest /= 56;
    int h = rest % 56;
    int b = rest / 56;
    size_t base = (((size_t)(b * Tt) * Hh + h) * Ww + w) * 64 + cp;   // in uint32 units
    const uint32_t* gp = (const uint32_t*)g_gateS;
    const uint32_t* hp = (const uint32_t*)g_hidS;
    uint32_t* ep = (uint32_t*)g_E;
    float H0 = 0.f, H1 = 0.f;
    #pragma unroll
    for (int t = 0; t < Tt; t++) {
        size_t off = base + (size_t)t * (HWC / 2);
        uint32_t gu = gp[off], hu = hp[off];
        float2 g2 = __bfloat1622float2(*(bf162*)&gu);
        float2 h2 = __bfloat1622float2(*(bf162*)&hu);
        // lane 0
        float e0 = exp_fast(-fabsf(g2.x));
        float r0 = rcp_fast(1.f + e0);
        float s0 = (g2.x >= 0.f) ? r0 : e0 * r0;     // sigmoid(g)
        float f0 = (g2.x >= 0.f) ? e0 * r0 : r0;     // sigmoid(-g)
        float v0 = (h2.x * h2.x + 1e-6f) * s0;
        H0 = fmaf(f0, H0, v0);
        // lane 1
        float e1 = exp_fast(-fabsf(g2.y));
        float r1 = rcp_fast(1.f + e1);
        float s1 = (g2.y >= 0.f) ? r1 : e1 * r1;
        float f1 = (g2.y >= 0.f) ? e1 * r1 : r1;
        float v1 = (h2.y * h2.y + 1e-6f) * s1;
        H1 = fmaf(f1, H1, v1);
        bf162 o = __floats2bfloat162_rn(H0, H1);
        ep[off] = *(uint32_t*)&o;
    }
}

// ---------------------------------------------------------------------------
// K4: ssm = E @ Wo + bo -> LayerNorm -> g_xn (bf16). 4 warps, n=32 each.
// ---------------------------------------------------------------------------
#define WO_SMEM (2*128*SA*2 + 128*129*4 + 3*128*4)
__global__ void __launch_bounds__(128) k_wo(const float* __restrict__ bo,
                                            const float* __restrict__ lns,
                                            const float* __restrict__ lnb) {
    extern __shared__ __align__(16) char sm[];
    bf16* As = (bf16*)sm;
    bf16* Bs = As + 128 * SA;
    float* stg = (float*)(Bs + 128 * SA);       // 128 x 129
    float* sbo = stg + 128 * 129;
    float* slns = sbo + 128;
    float* slnb = slns + 128;
    int tid = threadIdx.x, w = tid >> 5, l = tid & 31;
    size_t m0 = (size_t)blockIdx.x * 128;
    sbo[tid] = bo[tid]; slns[tid] = lns[tid]; slnb[tid] = lnb[tid];

    const uint4* ep = (const uint4*)(g_E + m0 * 128);
    const uint4* wop = (const uint4*)g_WoT;
    for (int idx = tid; idx < 128 * 16; idx += 128) {
        int r = idx >> 4, c = idx & 15;
        *(uint4*)(As + r * SA + c * 8) = ep[idx];
        *(uint4*)(Bs + r * SA + c * 8) = wop[idx];
    }
    __syncthreads();

    int wn0 = w * 32;
    uint32_t Abase = smem_u32(As) + ((l & 15) * SA + (l >> 4) * 8) * 2;
    uint32_t Bbase = smem_u32(Bs) + ((l & 15) * SA + (l >> 4) * 8) * 2 + wn0 * SA * 2;
    int quad = l >> 2, t4 = l & 3;

    for (int mc = 0; mc < 4; mc++) {
        float acc[2][4][4];
        #pragma unroll
        for (int mf = 0; mf < 2; mf++)
            #pragma unroll
            for (int nf = 0; nf < 4; nf++)
                #pragma unroll
                for (int e = 0; e < 4; e++) acc[mf][nf][e] = 0.f;
        #pragma unroll
        for (int k = 0; k < 8; k++) {
            uint32_t a[2][4], b[4][2];
            #pragma unroll
            for (int mf = 0; mf < 2; mf++)
                LDSM4(a[mf][0], a[mf][1], a[mf][2], a[mf][3],
                      Abase + (mc * 32 + mf * 16) * SA * 2 + k * 32);
            #pragma unroll
            for (int nf2 = 0; nf2 < 2; nf2++) {
                uint32_t r0, r1, r2, r3;
                LDSM4(r0, r1, r2, r3, Bbase + nf2 * 16 * SA * 2 + k * 32);
                b[nf2 * 2][0] = r0; b[nf2 * 2][1] = r2;
                b[nf2 * 2 + 1][0] = r1; b[nf2 * 2 + 1][1] = r3;
            }
            #pragma unroll
            for (int mf = 0; mf < 2; mf++)
                #pragma unroll
                for (int nf = 0; nf < 4; nf++) MMA16816(acc[mf][nf], a[mf], b[nf]);
        }
        #pragma unroll
        for (int mf = 0; mf < 2; mf++)
            #pragma unroll
            for (int nf = 0; nf < 4; nf++) {
                int n = wn0 + nf * 8 + t4 * 2;
                int r0 = mc * 32 + mf * 16 + quad;
                stg[r0 * 129 + n] = acc[mf][nf][0] + sbo[n];
                stg[r0 * 129 + n + 1] = acc[mf][nf][1] + sbo[n + 1];
                stg[(r0 + 8) * 129 + n] = acc[mf][nf][2] + sbo[n];
                stg[(r0 + 8) * 129 + n + 1] = acc[mf][nf][3] + sbo[n + 1];
            }
    }
    __syncthreads();
    float sum = 0.f, sq = 0.f;
    #pragma unroll 8
    for (int c = 0; c < 128; c++) {
        float v = stg[tid * 129 + c];
        sum += v; sq += v * v;
    }
    float mean = sum * (1.f / 128.f);
    float var = sq * (1.f / 128.f) - mean * mean;
    float rstd = rsqrtf(var + 1e-6f);
    bf162* dst = (bf162*)(g_xn + (m0 + tid) * 128);
    #pragma unroll 8
    for (int cp = 0; cp < 64; cp++) {
        int c = cp * 2;
        float a = (stg[tid * 129 + c] - mean) * rstd * slns[c] + slnb[c];
        float b = (stg[tid * 129 + c + 1] - mean) * rstd * slns[c + 1] + slnb[c + 1];
        dst[cp] = __floats2bfloat162_rn(a, b);
    }
}

// ---------------------------------------------------------------------------
// K5: MLP1  xn[128,128] @ W1 -> gelu(tanh.approx) -> g_hidden (bf16)
// ---------------------------------------------------------------------------
#define M1_SMEM (128*SA*2 + 512*SA*2 + 512*4)
__global__ void __launch_bounds__(256) k_mlp1(const float* __restrict__ b1) {
    extern __shared__ __align__(16) char sm[];
    bf16* As = (bf16*)sm;
    bf16* Bs = As + 128 * SA;
    float* sb1 = (float*)(Bs + 512 * SA);
    int tid = threadIdx.x, w = tid >> 5, l = tid & 31;
    size_t m0 = (size_t)blockIdx.x * 128;
    sb1[tid] = b1[tid]; sb1[256 + tid] = b1[256 + tid];

    const uint4* xp = (const uint4*)(g_xn + m0 * 128);
    for (int idx = tid; idx < 128 * 16; idx += 256) {
        int r = idx >> 4, c = idx & 15;
        *(uint4*)(As + r * SA + c * 8) = xp[idx];
    }
    const uint4* w1p = (const uint4*)g_W1T;
    for (int idx = tid; idx < 512 * 16; idx += 256) {
        int r = idx >> 4, c = idx & 15;
        *(uint4*)(Bs + r * SA + c * 8) = w1p[idx];
    }
    __syncthreads();

    int wn0 = w * 64;
    uint32_t Abase = smem_u32(As) + ((l & 15) * SA + (l >> 4) * 8) * 2;
    uint32_t Bbase = smem_u32(Bs) + ((l & 15) * SA + (l >> 4) * 8) * 2 + wn0 * SA * 2;
    int quad = l >> 2, t4 = l & 3;

    for (int mc = 0; mc < 4; mc++) {
        float acc[2][8][4];
        #pragma unroll
        for (int mf = 0; mf < 2; mf++)
            #pragma unroll
            for (int nf = 0; nf < 8; nf++)
                #pragma unroll
                for (int e = 0; e < 4; e++) acc[mf][nf][e] = 0.f;
        #pragma unroll
        for (int k = 0; k < 8; k++) {
            uint32_t a[2][4], b[8][2];
            #pragma unroll
            for (int mf = 0; mf < 2; mf++)
                LDSM4(a[mf][0], a[mf][1], a[mf][2], a[mf][3],
                      Abase + (mc * 32 + mf * 16) * SA * 2 + k * 32);
            #pragma unroll
            for (int nf2 = 0; nf2 < 4; nf2++) {
                uint32_t r0, r1, r2, r3;
                LDSM4(r0, r1, r2, r3, Bbase + nf2 * 16 * SA * 2 + k * 32);
                b[nf2 * 2][0] = r0; b[nf2 * 2][1] = r2;
                b[nf2 * 2 + 1][0] = r1; b[nf2 * 2 + 1][1] = r3;
            }
            #pragma unroll
            for (int mf = 0; mf < 2; mf++)
                #pragma unroll
                for (int nf = 0; nf < 8; nf++) MMA16816(acc[mf][nf], a[mf], b[nf]);
        }
        #pragma unroll
        for (int mf = 0; mf < 2; mf++)
            #pragma unroll
            for (int nf = 0; nf < 8; nf++) {
                int n = wn0 + nf * 8 + t4 * 2;
                int r0 = mc * 32 + mf * 16 + quad;
                #pragma unroll
                for (int hrow = 0; hrow < 2; hrow++) {
                    float v0 = acc[mf][nf][hrow * 2] + sb1[n];
                    float v1 = acc[mf][nf][hrow * 2 + 1] + sb1[n + 1];
                    float t0 = tanh_fast(0.7978845608028654f * (v0 + 0.044715f * v0 * v0 * v0));
                    float t1 = tanh_fast(0.7978845608028654f * (v1 + 0.044715f * v1 * v1 * v1));
                    *(bf162*)(g_hidden + (m0 + r0 + hrow * 8) * 512 + n) =
                        __floats2bfloat162_rn(0.5f * v0 * (1.f + t0), 0.5f * v1 * (1.f + t1));
                }
            }
    }
}

// ---------------------------------------------------------------------------
// K6: MLP2  hidden[128,512] @ W2 (K split 2x256) + gamma*.. + x -> out (f32)
// ---------------------------------------------------------------------------
#define M2_SMEM (2*128*SA2*2 + 256*4)
__global__ void __launch_bounds__(256) k_mlp2(const float* __restrict__ x,
                                              const float* __restrict__ b2,
                                              const float* __restrict__ gamma,
                                              float* __restrict__ out) {
    extern __shared__ __align__(16) char sm[];
    bf16* As = (bf16*)sm;
    bf16* Bs = As + 128 * SA2;
    float* sb2 = (float*)(Bs + 128 * SA2);
    float* sgm = sb2 + 128;
    int tid = threadIdx.x, w = tid >> 5, l = tid & 31;
    size_t m0 = (size_t)blockIdx.x * 128;
    if (tid < 128) { sb2[tid] = b2[tid]; sgm[tid] = gamma[tid]; }

    int wn0 = w * 16;
    uint32_t Ab = smem_u32(As) + ((l & 15) * SA2 + (l >> 4) * 8) * 2;
    uint32_t Bb_ = smem_u32(Bs) + ((l & 15) * SA2 + (l >> 4) * 8) * 2 + wn0 * SA2 * 2;
    int quad = l >> 2, t4 = l & 3;

    float acc[4][2][2][4];
    #pragma unroll
    for (int mc = 0; mc < 4; mc++)
        #pragma unroll
        for (int mf = 0; mf < 2; mf++)
            #pragma unroll
            for (int nf = 0; nf < 2; nf++)
                #pragma unroll
                for (int e = 0; e < 4; e++) acc[mc][mf][nf][e] = 0.f;

    const uint4* hp = (const uint4*)g_hidden;
    const uint4* w2p = (const uint4*)g_W2T;
    for (int ph = 0; ph < 2; ph++) {
        if (ph) __syncthreads();
        for (int idx = tid; idx < 128 * 32; idx += 256) {
            int r = idx >> 5, c = idx & 31;
            *(uint4*)(As + r * SA2 + c * 8) = hp[(m0 + r) * 64 + ph * 32 + c];
            *(uint4*)(Bs + r * SA2 + c * 8) = w2p[(size_t)r * 64 + ph * 32 + c];
        }
        __syncthreads();
        for (int mc = 0; mc < 4; mc++) {
            #pragma unroll
            for (int k = 0; k < 16; k++) {
                uint32_t a[2][4], b[2][2];
                #pragma unroll
                for (int mf = 0; mf < 2; mf++)
                    LDSM4(a[mf][0], a[mf][1], a[mf][2], a[mf][3],
                          Ab + (mc * 32 + mf * 16) * SA2 * 2 + k * 32);
                uint32_t r0, r1, r2, r3;
                LDSM4(r0, r1, r2, r3, Bb_ + k * 32);
                b[0][0] = r0; b[0][1] = r2;
                b[1][0] = r1; b[1][1] = r3;
                #pragma unroll
                for (int mf = 0; mf < 2; mf++)
                    #pragma unroll
                    for (int nf = 0; nf < 2; nf++) MMA16816(acc[mc][mf][nf], a[mf], b[nf]);
            }
        }
    }
    #pragma unroll
    for (int mc = 0; mc < 4; mc++)
        #pragma unroll
        for (int mf = 0; mf < 2; mf++)
            #pragma unroll
            for (int nf = 0; nf < 2; nf++) {
                int n = wn0 + nf * 8 + t4 * 2;
                size_t r0 = m0 + mc * 32 + mf * 16 + quad;
                #pragma unroll
                for (int hrow = 0; hrow < 2; hrow++) {
                    size_t r = r0 + hrow * 8;
                    float v0 = (acc[mc][mf][nf][hrow * 2] + sb2[n]) * sgm[n] + x[r * 128 + n];
                    float v1 = (acc[mc][mf][nf][hrow * 2 + 1] + sb2[n + 1]) * sgm[n + 1] + x[r * 128 + n + 1];
                    out[r * 128 + n] = v0;
                    out[r * 128 + n + 1] = v1;
                }
            }
}

// ---------------------------------------------------------------------------
extern "C" void kernel_launch(void* const* d_in, const int* in_sizes, int n_in,
                              void* d_out, int out_size) {
    const float* x     = (const float*)d_in[0];
    const float* Wg    = (const float*)d_in[1];
    const float* bg    = (const float*)d_in[2];
    const float* Wh    = (const float*)d_in[3];
    const float* bh    = (const float*)d_in[4];
    const float* gk    = (const float*)d_in[5];
    const float* hk    = (const float*)d_in[6];
    const float* Wo    = (const float*)d_in[7];
    const float* bo    = (const float*)d_in[8];
    const float* lns   = (const float*)d_in[9];
    const float* lnb   = (const float*)d_in[10];
    const float* W1    = (const float*)d_in[11];
    const float* b1    = (const float*)d_in[12];
    const float* W2    = (const float*)d_in[13];
    const float* b2    = (const float*)d_in[14];
    const float* gamma = (const float*)d_in[15];
    float* out = (float*)d_out;

    cudaFuncSetAttribute(k_proj, cudaFuncAttributeMaxDynamicSharedMemorySize, PROJ_SMEM);
    cudaFuncSetAttribute(k_wo,   cudaFuncAttributeMaxDynamicSharedMemorySize, WO_SMEM);
    cudaFuncSetAttribute(k_mlp1, cudaFuncAttributeMaxDynamicSharedMemorySize, M1_SMEM);
    cudaFuncSetAttribute(k_mlp2, cudaFuncAttributeMaxDynamicSharedMemorySize, M2_SMEM);

    k_prep<<<256, 256>>>(Wg, Wh, Wo, W1, W2, gk, hk);
    k_proj<<<NTILES, 128, PROJ_SMEM>>>(x, bg, bh);
    k_conv<<<dim3(Hh * Bb * Tt, 1, 2), dim3(32, 4)>>>();
    k_scan<<<(Bb * Hh * Ww * 64) / 256, 256>>>();
    k_wo<<<NTILES, 128, WO_SMEM>>>(bo, lns, lnb);
    k_mlp1<<<NTILES, 256, M1_SMEM>>>(b1);
    k_mlp2<<<NTILES, 256, M2_SMEM>>>(x, b2, gamma, out);
}

// round 5
// speedup vs baseline: 2.7602x; 1.0225x over previous
#include <cuda_runtime.h>
#include <cuda_bf16.h>
#include <math.h>
#include <stdint.h>

#define Bb 2
#define Tt 16
#define Hh 56
#define Ww 56
#define Cc 128
#define NPTS (Bb*Tt*Hh*Ww)          /* 100352 */
#define TOT  (NPTS*Cc)              /* 12845056 */
#define HWC  (Hh*Ww*Cc)
#define KTAPS 245
#define NTILES (NPTS/128)           /* 784 */

typedef __nv_bfloat16 bf16;
typedef __nv_bfloat162 bf162;

// ---------------- device scratch (allocation-free) ----------------
__device__ __align__(16) bf16 g_gateP[TOT];
__device__ __align__(16) bf16 g_hidP[TOT];
__device__ __align__(16) bf16 g_gateS[TOT];
__device__ __align__(16) bf16 g_hidS[TOT];
__device__ __align__(16) bf16 g_E[TOT];
__device__ __align__(16) bf16 g_xn[TOT];
__device__ __align__(16) bf16 g_WgT[Cc*Cc];       // [n][k]
__device__ __align__(16) bf16 g_WhT[Cc*Cc];
__device__ __align__(16) bf16 g_WoT[Cc*Cc];
__device__ __align__(16) bf16 g_W1T[512*Cc];      // [n=512][k=128]
__device__ __align__(16) bf16 g_W2T[Cc*512];      // [n=128][k=512]
__device__ __align__(16) bf16 g_kB[2][KTAPS*Cc];  // [tap][c]

// ---------------- helpers ----------------
__device__ __forceinline__ uint32_t smem_u32(const void* p) {
    uint32_t a;
    asm("{ .reg .u64 t; cvta.to.shared.u64 t, %1; cvt.u32.u64 %0, t; }" : "=r"(a) : "l"(p));
    return a;
}
#define LDSM4(r0, r1, r2, r3, a) \
    asm volatile("ldmatrix.sync.aligned.m8n8.x4.shared.b16 {%0,%1,%2,%3}, [%4];" \
        : "=r"(r0), "=r"(r1), "=r"(r2), "=r"(r3) : "r"(a))
#define MMA16816(c, a, b) \
    asm volatile("mma.sync.aligned.m16n8k16.row.col.f32.bf16.bf16.f32 " \
        "{%0,%1,%2,%3},{%4,%5,%6,%7},{%8,%9},{%0,%1,%2,%3};" \
        : "+f"((c)[0]), "+f"((c)[1]), "+f"((c)[2]), "+f"((c)[3]) \
        : "r"((a)[0]), "r"((a)[1]), "r"((a)[2]), "r"((a)[3]), "r"((b)[0]), "r"((b)[1]))

__device__ __forceinline__ float tanh_fast(float x) {
    float y;
    asm("tanh.approx.f32 %0, %1;" : "=f"(y) : "f"(x));
    return y;
}
__device__ __forceinline__ float exp_fast(float x) {
    float y;
    asm("ex2.approx.f32 %0, %1;" : "=f"(y) : "f"(x * 1.4426950408889634f));
    return y;
}
__device__ __forceinline__ float rcp_fast(float x) {
    float y;
    asm("rcp.approx.f32 %0, %1;" : "=f"(y) : "f"(x));
    return y;
}

#define SA 136    /* smem row stride (bf16 elems) for 128-col tiles */
#define SH 520    /* smem row stride for hidden (512-col) tile */

// ---------------------------------------------------------------------------
// K0: weight prep — transposed bf16 copies of all weights + conv kernels
// ---------------------------------------------------------------------------
__global__ void k_prep(const float* __restrict__ Wg, const float* __restrict__ Wh,
                       const float* __restrict__ Wo, const float* __restrict__ W1,
                       const float* __restrict__ W2, const float* __restrict__ gk,
                       const float* __restrict__ hk) {
    int i = blockIdx.x * 256 + threadIdx.x;
    if (i < 16384) {
        int n = i >> 7, k = i & 127;
        g_WgT[i] = __float2bfloat16(Wg[k * 128 + n]);
        g_WhT[i] = __float2bfloat16(Wh[k * 128 + n]);
        g_WoT[i] = __float2bfloat16(Wo[k * 128 + n]);
    }
    if (i < 65536) {
        int n = i >> 7, k = i & 127;
        g_W1T[i] = __float2bfloat16(W1[k * 512 + n]);
        int n2 = i >> 9, k2 = i & 511;
        g_W2T[i] = __float2bfloat16(W2[k2 * 128 + n2]);
    }
    if (i < 2 * KTAPS * 128) {
        int which = i / (KTAPS * 128);
        int j = i - which * (KTAPS * 128);
        int tap = j >> 7, c = j & 127;
        const float* s = which ? hk : gk;
        g_kB[which][j] = __float2bfloat16(s[c * KTAPS + tap]);
    }
}

// ---------------------------------------------------------------------------
// K1: dual projection  [128,128] x (Wg | Wh) -> g_gateP, g_hidP (bf16)
// ---------------------------------------------------------------------------
#define PROJ_SMEM (3*128*SA*2 + 256*4)
__global__ void __launch_bounds__(128) k_proj(const float* __restrict__ x,
                                              const float* __restrict__ bg,
                                              const float* __restrict__ bh) {
    extern __shared__ __align__(16) char sm[];
    bf16* As = (bf16*)sm;                       // 128 x SA
    bf16* Bs = As + 128 * SA;                   // 2 x (128 x SA)
    float* sbias = (float*)(Bs + 2 * 128 * SA); // 256 floats
    int tid = threadIdx.x, w = tid >> 5, l = tid & 31;
    size_t m0 = (size_t)blockIdx.x * 128;
    sbias[tid] = bg[tid];
    sbias[128 + tid] = bh[tid];

    const float2* xs = (const float2*)(x + m0 * 128);
    for (int idx = tid; idx < 128 * 64; idx += 128) {
        int r = idx >> 6, cp = idx & 63;
        float2 v = xs[idx];
        *(bf162*)(As + r * SA + cp * 2) = __floats2bfloat162_rn(v.x, v.y);
    }
    const uint4* wgp = (const uint4*)g_WgT;
    const uint4* whp = (const uint4*)g_WhT;
    for (int idx = tid; idx < 128 * 16; idx += 128) {
        int r = idx >> 4, c = idx & 15;
        *(uint4*)(Bs + r * SA + c * 8) = wgp[idx];
        *(uint4*)(Bs + 128 * SA + r * SA + c * 8) = whp[idx];
    }
    __syncthreads();

    int which = w >> 1;
    int wn0 = (w & 1) * 64;
    uint32_t Abase = smem_u32(As) + ((l & 15) * SA + (l >> 4) * 8) * 2;
    uint32_t Bbase = smem_u32(Bs + which * 128 * SA) + ((l & 15) * SA + (l >> 4) * 8) * 2 + wn0 * SA * 2;
    bf16* outb = which ? g_hidP : g_gateP;
    float* bb = sbias + which * 128;
    int quad = l >> 2, t4 = l & 3;

    for (int mc = 0; mc < 4; mc++) {
        float acc[2][8][4];
        #pragma unroll
        for (int mf = 0; mf < 2; mf++)
            #pragma unroll
            for (int nf = 0; nf < 8; nf++)
                #pragma unroll
                for (int e = 0; e < 4; e++) acc[mf][nf][e] = 0.f;
        #pragma unroll
        for (int k = 0; k < 8; k++) {
            uint32_t a[2][4], b[8][2];
            #pragma unroll
            for (int mf = 0; mf < 2; mf++)
                LDSM4(a[mf][0], a[mf][1], a[mf][2], a[mf][3],
                      Abase + (mc * 32 + mf * 16) * SA * 2 + k * 32);
            #pragma unroll
            for (int nf2 = 0; nf2 < 4; nf2++) {
                uint32_t r0, r1, r2, r3;
                LDSM4(r0, r1, r2, r3, Bbase + nf2 * 16 * SA * 2 + k * 32);
                b[nf2 * 2][0] = r0; b[nf2 * 2][1] = r2;
                b[nf2 * 2 + 1][0] = r1; b[nf2 * 2 + 1][1] = r3;
            }
            #pragma unroll
            for (int mf = 0; mf < 2; mf++)
                #pragma unroll
                for (int nf = 0; nf < 8; nf++) MMA16816(acc[mf][nf], a[mf], b[nf]);
        }
        #pragma unroll
        for (int mf = 0; mf < 2; mf++)
            #pragma unroll
            for (int nf = 0; nf < 8; nf++) {
                int n = wn0 + nf * 8 + t4 * 2;
                int r0 = mc * 32 + mf * 16 + quad;
                *(bf162*)(outb + (m0 + r0) * 128 + n) =
                    __floats2bfloat162_rn(acc[mf][nf][0] + bb[n], acc[mf][nf][1] + bb[n + 1]);
                *(bf162*)(outb + (m0 + r0 + 8) * 128 + n) =
                    __floats2bfloat162_rn(acc[mf][nf][2] + bb[n], acc[mf][nf][3] + bb[n + 1]);
            }
    }
}

// ---------------------------------------------------------------------------
// K2: depthwise circular conv 5x7x7, bf16 HFMA2
// ---------------------------------------------------------------------------
__global__ void __launch_bounds__(128) k_conv(void) {
    int ct = threadIdx.x;
    int wq = threadIdx.y;
    int which = blockIdx.z;
    const uint2* __restrict__ in = (const uint2*)(which ? g_hidP : g_gateP);
    uint2* __restrict__ outp = (uint2*)(which ? g_hidS : g_gateS);
    const uint2* __restrict__ kt = (const uint2*)g_kB[which];
    int w0 = wq * 14;
    int hbt = blockIdx.x;
    int h = hbt % Hh;
    int bt = hbt / Hh;
    int t = bt & 15;
    int bbase = bt - t;

    bf162 acc[14][2];
    bf162 z = __floats2bfloat162_rn(0.f, 0.f);
    #pragma unroll
    for (int i = 0; i < 14; i++) { acc[i][0] = z; acc[i][1] = z; }

    for (int ktp = 0; ktp < 5; ktp++) {
        int tin = (t - ktp + 18) & 15;
        int btin = bbase + tin;
        for (int kh = 0; kh < 7; kh++) {
            int hin = h - kh + 3;
            if (hin < 0)   hin += 56;
            if (hin >= 56) hin -= 56;
            const uint2* src = in + (size_t)(btin * Hh + hin) * (Ww * 32) + ct;
            uint2 win[20];
            #pragma unroll
            for (int j = 0; j < 20; j++) {
                int wi = w0 - 3 + j;
                if (wi < 0)   wi += 56;
                if (wi >= 56) wi -= 56;
                win[j] = src[(size_t)wi * 32];
            }
            const uint2* kb = kt + (size_t)(ktp * 49 + kh * 7) * 32 + ct;
            uint2 kv[7];
            #pragma unroll
            for (int kw = 0; kw < 7; kw++) kv[kw] = kb[(size_t)kw * 32];
            #pragma unroll
            for (int i = 0; i < 14; i++) {
                #pragma unroll
                for (int kw = 0; kw < 7; kw++) {
                    bf162 klo = *(bf162*)&kv[kw].x;
                    bf162 khi = *(bf162*)&kv[kw].y;
                    bf162 wlo = *(bf162*)&win[i + 6 - kw].x;
                    bf162 whi = *(bf162*)&win[i + 6 - kw].y;
                    acc[i][0] = __hfma2(klo, wlo, acc[i][0]);
                    acc[i][1] = __hfma2(khi, whi, acc[i][1]);
                }
            }
        }
    }
    uint2* dst = outp + ((size_t)(bt * Hh + h) * Ww + w0) * 32 + ct;
    #pragma unroll
    for (int i = 0; i < 14; i++) {
        uint2 v;
        v.x = *(uint32_t*)&acc[i][0];
        v.y = *(uint32_t*)&acc[i][1];
        dst[(size_t)i * 32] = v;
    }
}

// ---------------------------------------------------------------------------
// K3: LINEAR-domain Heinsen scan: H_t = sigmoid(-g)*H_{t-1} + sigmoid(g)*(h^2+1e-6)
// ---------------------------------------------------------------------------
__global__ void k_scan(void) {
    int idx = blockIdx.x * 256 + threadIdx.x;
    int cp = idx & 63;
    int rest = idx >> 6;
    int w = rest % 56; rest /= 56;
    int h = rest % 56;
    int b = rest / 56;
    size_t base = (((size_t)(b * Tt) * Hh + h) * Ww + w) * 64 + cp;
    const uint32_t* gp = (const uint32_t*)g_gateS;
    const uint32_t* hp = (const uint32_t*)g_hidS;
    uint32_t* ep = (uint32_t*)g_E;
    float H0 = 0.f, H1 = 0.f;
    #pragma unroll
    for (int t = 0; t < Tt; t++) {
        size_t off = base + (size_t)t * (HWC / 2);
        uint32_t gu = gp[off], hu = hp[off];
        float2 g2 = __bfloat1622float2(*(bf162*)&gu);
        float2 h2 = __bfloat1622float2(*(bf162*)&hu);
        float e0 = exp_fast(-fabsf(g2.x));
        float r0 = rcp_fast(1.f + e0);
        float s0 = (g2.x >= 0.f) ? r0 : e0 * r0;
        float f0 = (g2.x >= 0.f) ? e0 * r0 : r0;
        float v0 = (h2.x * h2.x + 1e-6f) * s0;
        H0 = fmaf(f0, H0, v0);
        float e1 = exp_fast(-fabsf(g2.y));
        float r1 = rcp_fast(1.f + e1);
        float s1 = (g2.y >= 0.f) ? r1 : e1 * r1;
        float f1 = (g2.y >= 0.f) ? e1 * r1 : r1;
        float v1 = (h2.y * h2.y + 1e-6f) * s1;
        H1 = fmaf(f1, H1, v1);
        bf162 o = __floats2bfloat162_rn(H0, H1);
        ep[off] = *(uint32_t*)&o;
    }
}

// ---------------------------------------------------------------------------
// K4: ssm = E @ Wo + bo -> LayerNorm -> g_xn (bf16). 4 warps, n=32 each.
// ---------------------------------------------------------------------------
#define WO_SMEM (2*128*SA*2 + 128*129*4 + 3*128*4)
__global__ void __launch_bounds__(128) k_wo(const float* __restrict__ bo,
                                            const float* __restrict__ lns,
                                            const float* __restrict__ lnb) {
    extern __shared__ __align__(16) char sm[];
    bf16* As = (bf16*)sm;
    bf16* Bs = As + 128 * SA;
    float* stg = (float*)(Bs + 128 * SA);       // 128 x 129
    float* sbo = stg + 128 * 129;
    float* slns = sbo + 128;
    float* slnb = slns + 128;
    int tid = threadIdx.x, w = tid >> 5, l = tid & 31;
    size_t m0 = (size_t)blockIdx.x * 128;
    sbo[tid] = bo[tid]; slns[tid] = lns[tid]; slnb[tid] = lnb[tid];

    const uint4* ep = (const uint4*)(g_E + m0 * 128);
    const uint4* wop = (const uint4*)g_WoT;
    for (int idx = tid; idx < 128 * 16; idx += 128) {
        int r = idx >> 4, c = idx & 15;
        *(uint4*)(As + r * SA + c * 8) = ep[idx];
        *(uint4*)(Bs + r * SA + c * 8) = wop[idx];
    }
    __syncthreads();

    int wn0 = w * 32;
    uint32_t Abase = smem_u32(As) + ((l & 15) * SA + (l >> 4) * 8) * 2;
    uint32_t Bbase = smem_u32(Bs) + ((l & 15) * SA + (l >> 4) * 8) * 2 + wn0 * SA * 2;
    int quad = l >> 2, t4 = l & 3;

    for (int mc = 0; mc < 4; mc++) {
        float acc[2][4][4];
        #pragma unroll
        for (int mf = 0; mf < 2; mf++)
            #pragma unroll
            for (int nf = 0; nf < 4; nf++)
                #pragma unroll
                for (int e = 0; e < 4; e++) acc[mf][nf][e] = 0.f;
        #pragma unroll
        for (int k = 0; k < 8; k++) {
            uint32_t a[2][4], b[4][2];
            #pragma unroll
            for (int mf = 0; mf < 2; mf++)
                LDSM4(a[mf][0], a[mf][1], a[mf][2], a[mf][3],
                      Abase + (mc * 32 + mf * 16) * SA * 2 + k * 32);
            #pragma unroll
            for (int nf2 = 0; nf2 < 2; nf2++) {
                uint32_t r0, r1, r2, r3;
                LDSM4(r0, r1, r2, r3, Bbase + nf2 * 16 * SA * 2 + k * 32);
                b[nf2 * 2][0] = r0; b[nf2 * 2][1] = r2;
                b[nf2 * 2 + 1][0] = r1; b[nf2 * 2 + 1][1] = r3;
            }
            #pragma unroll
            for (int mf = 0; mf < 2; mf++)
                #pragma unroll
                for (int nf = 0; nf < 4; nf++) MMA16816(acc[mf][nf], a[mf], b[nf]);
        }
        #pragma unroll
        for (int mf = 0; mf < 2; mf++)
            #pragma unroll
            for (int nf = 0; nf < 4; nf++) {
                int n = wn0 + nf * 8 + t4 * 2;
                int r0 = mc * 32 + mf * 16 + quad;
                stg[r0 * 129 + n] = acc[mf][nf][0] + sbo[n];
                stg[r0 * 129 + n + 1] = acc[mf][nf][1] + sbo[n + 1];
                stg[(r0 + 8) * 129 + n] = acc[mf][nf][2] + sbo[n];
                stg[(r0 + 8) * 129 + n + 1] = acc[mf][nf][3] + sbo[n + 1];
            }
    }
    __syncthreads();
    float sum = 0.f, sq = 0.f;
    #pragma unroll 8
    for (int c = 0; c < 128; c++) {
        float v = stg[tid * 129 + c];
        sum += v; sq += v * v;
    }
    float mean = sum * (1.f / 128.f);
    float var = sq * (1.f / 128.f) - mean * mean;
    float rstd = rsqrtf(var + 1e-6f);
    bf162* dst = (bf162*)(g_xn + (m0 + tid) * 128);
    #pragma unroll 8
    for (int cp = 0; cp < 64; cp++) {
        int c = cp * 2;
        float a = (stg[tid * 129 + c] - mean) * rstd * slns[c] + slnb[c];
        float b = (stg[tid * 129 + c + 1] - mean) * rstd * slns[c + 1] + slnb[c + 1];
        dst[cp] = __floats2bfloat162_rn(a, b);
    }
}

// ---------------------------------------------------------------------------
// K5: FUSED MLP  xn[128,128] -> gelu(xn@W1+b1) in smem -> @W2+b2 -> *gamma + x
// 256 threads, 8 warps as 4m x 2n; hidden (128x512 bf16) resident in smem.
// W1 streamed in 4 n-chunks, W2 in 4 k-chunks through one 32KB slot.
// ---------------------------------------------------------------------------
#define MF_SMEM (128*SA*2 + 128*SA*2 + 128*SH*2 + 768*4)
__global__ void __launch_bounds__(256) k_mlp(const float* __restrict__ x,
                                             const float* __restrict__ b1,
                                             const float* __restrict__ b2,
                                             const float* __restrict__ gamma,
                                             float* __restrict__ out) {
    extern __shared__ __align__(16) char sm[];
    bf16* As = (bf16*)sm;              // xn tile: 128 x SA
    bf16* Bs = As + 128 * SA;          // W chunk: 128 x SA
    bf16* Hs = Bs + 128 * SA;          // hidden: 128 x SH
    float* sb1 = (float*)(Hs + 128 * SH);  // 512
    float* sb2 = sb1 + 512;                // 128
    float* sgm = sb2 + 128;                // 128
    int tid = threadIdx.x, w = tid >> 5, l = tid & 31;
    int wm = w >> 1, wn = w & 1;
    int quad = l >> 2, t4 = l & 3;
    size_t m0 = (size_t)blockIdx.x * 128;

    sb1[tid] = b1[tid]; sb1[256 + tid] = b1[256 + tid];
    if (tid < 128) { sb2[tid] = b2[tid]; sgm[tid] = gamma[tid]; }

    const uint4* xp = (const uint4*)(g_xn + m0 * 128);
    for (int idx = tid; idx < 128 * 16; idx += 256) {
        int r = idx >> 4, c = idx & 15;
        *(uint4*)(As + r * SA + c * 8) = xp[idx];
    }

    uint32_t Abase = smem_u32(As) + ((l & 15) * SA + (l >> 4) * 8) * 2 + (wm * 32) * SA * 2;
    uint32_t Bbase = smem_u32(Bs) + ((l & 15) * SA + (l >> 4) * 8) * 2 + (wn * 64) * SA * 2;
    uint32_t Hbase = smem_u32(Hs) + ((l & 15) * SH + (l >> 4) * 8) * 2 + (wm * 32) * SH * 2;

    // ---------------- stage 1: hidden = gelu(xn @ W1 + b1) -> Hs ----------------
    const uint4* w1p = (const uint4*)g_W1T;   // [n=512][k=128]
    for (int nc = 0; nc < 4; nc++) {
        __syncthreads();    // As ready (first iter) / prior Bs reads done
        for (int idx = tid; idx < 128 * 16; idx += 256) {
            int r = idx >> 4, c = idx & 15;
            *(uint4*)(Bs + r * SA + c * 8) = w1p[(nc * 128 + r) * 16 + c];
        }
        __syncthreads();

        float acc[2][8][4];
        #pragma unroll
        for (int mf = 0; mf < 2; mf++)
            #pragma unroll
            for (int nf = 0; nf < 8; nf++)
                #pragma unroll
                for (int e = 0; e < 4; e++) acc[mf][nf][e] = 0.f;
        #pragma unroll
        for (int k = 0; k < 8; k++) {
            uint32_t a[2][4], b[8][2];
            #pragma unroll
            for (int mf = 0; mf < 2; mf++)
                LDSM4(a[mf][0], a[mf][1], a[mf][2], a[mf][3],
                      Abase + mf * 16 * SA * 2 + k * 32);
            #pragma unroll
            for (int nf2 = 0; nf2 < 4; nf2++) {
                uint32_t r0, r1, r2, r3;
                LDSM4(r0, r1, r2, r3, Bbase + nf2 * 16 * SA * 2 + k * 32);
                b[nf2 * 2][0] = r0; b[nf2 * 2][1] = r2;
                b[nf2 * 2 + 1][0] = r1; b[nf2 * 2 + 1][1] = r3;
            }
            #pragma unroll
            for (int mf = 0; mf < 2; mf++)
                #pragma unroll
                for (int nf = 0; nf < 8; nf++) MMA16816(acc[mf][nf], a[mf], b[nf]);
        }
        #pragma unroll
        for (int mf = 0; mf < 2; mf++)
            #pragma unroll
            for (int nf = 0; nf < 8; nf++) {
                int nl = wn * 64 + nf * 8 + t4 * 2;
                int ng = nc * 128 + nl;
                int r0 = wm * 32 + mf * 16 + quad;
                #pragma unroll
                for (int hrow = 0; hrow < 2; hrow++) {
                    float v0 = acc[mf][nf][hrow * 2] + sb1[ng];
                    float v1 = acc[mf][nf][hrow * 2 + 1] + sb1[ng + 1];
                    float t0 = tanh_fast(0.7978845608028654f * (v0 + 0.044715f * v0 * v0 * v0));
                    float t1 = tanh_fast(0.7978845608028654f * (v1 + 0.044715f * v1 * v1 * v1));
                    *(bf162*)(Hs + (r0 + hrow * 8) * SH + ng) =
                        __floats2bfloat162_rn(0.5f * v0 * (1.f + t0), 0.5f * v1 * (1.f + t1));
                }
            }
    }

    // ---------------- stage 2: y = hidden @ W2 (K=512, 4 chunks) ----------------
    float acc2[2][8][4];
    #pragma unroll
    for (int mf = 0; mf < 2; mf++)
        #pragma unroll
        for (int nf = 0; nf < 8; nf++)
            #pragma unroll
            for (int e = 0; e < 4; e++) acc2[mf][nf][e] = 0.f;

    const uint4* w2p = (const uint4*)g_W2T;   // [n=128][k=512], 64 uint4/row
    for (int kc = 0; kc < 4; kc++) {
        __syncthreads();   // Hs writes visible (kc=0) / prior Bs reads done
        for (int idx = tid; idx < 128 * 16; idx += 256) {
            int r = idx >> 4, c = idx & 15;
            *(uint4*)(Bs + r * SA + c * 8) = w2p[(size_t)r * 64 + kc * 16 + c];
        }
        __syncthreads();
        #pragma unroll
        for (int k = 0; k < 8; k++) {
            uint32_t a[2][4], b[8][2];
            #pragma unroll
            for (int mf = 0; mf < 2; mf++)
                LDSM4(a[mf][0], a[mf][1], a[mf][2], a[mf][3],
                      Hbase + mf * 16 * SH * 2 + kc * 256 + k * 32);
            #pragma unroll
            for (int nf2 = 0; nf2 < 4; nf2++) {
                uint32_t r0, r1, r2, r3;
                LDSM4(r0, r1, r2, r3, Bbase + nf2 * 16 * SA * 2 + k * 32);
                b[nf2 * 2][0] = r0; b[nf2 * 2][1] = r2;
                b[nf2 * 2 + 1][0] = r1; b[nf2 * 2 + 1][1] = r3;
            }
            #pragma unroll
            for (int mf = 0; mf < 2; mf++)
                #pragma unroll
                for (int nf = 0; nf < 8; nf++) MMA16816(acc2[mf][nf], a[mf], b[nf]);
        }
    }

    // ---------------- epilogue: *gamma + residual -> out (f32) ----------------
    #pragma unroll
    for (int mf = 0; mf < 2; mf++)
        #pragma unroll
        for (int nf = 0; nf < 8; nf++) {
            int n = wn * 64 + nf * 8 + t4 * 2;
            size_t r0 = m0 + wm * 32 + mf * 16 + quad;
            #pragma unroll
            for (int hrow = 0; hrow < 2; hrow++) {
                size_t r = r0 + hrow * 8;
                float v0 = (acc2[mf][nf][hrow * 2] + sb2[n]) * sgm[n] + x[r * 128 + n];
                float v1 = (acc2[mf][nf][hrow * 2 + 1] + sb2[n + 1]) * sgm[n + 1] + x[r * 128 + n + 1];
                out[r * 128 + n] = v0;
                out[r * 128 + n + 1] = v1;
            }
        }
}

// ---------------------------------------------------------------------------
extern "C" void kernel_launch(void* const* d_in, const int* in_sizes, int n_in,
                              void* d_out, int out_size) {
    const float* x     = (const float*)d_in[0];
    const float* Wg    = (const float*)d_in[1];
    const float* bg    = (const float*)d_in[2];
    const float* Wh    = (const float*)d_in[3];
    const float* bh    = (const float*)d_in[4];
    const float* gk    = (const float*)d_in[5];
    const float* hk    = (const float*)d_in[6];
    const float* Wo    = (const float*)d_in[7];
    const float* bo    = (const float*)d_in[8];
    const float* lns   = (const float*)d_in[9];
    const float* lnb   = (const float*)d_in[10];
    const float* W1    = (const float*)d_in[11];
    const float* b1    = (const float*)d_in[12];
    const float* W2    = (const float*)d_in[13];
    const float* b2    = (const float*)d_in[14];
    const float* gamma = (const float*)d_in[15];
    float* out = (float*)d_out;

    cudaFuncSetAttribute(k_proj, cudaFuncAttributeMaxDynamicSharedMemorySize, PROJ_SMEM);
    cudaFuncSetAttribute(k_wo,   cudaFuncAttributeMaxDynamicSharedMemorySize, WO_SMEM);
    cudaFuncSetAttribute(k_mlp,  cudaFuncAttributeMaxDynamicSharedMemorySize, MF_SMEM);

    k_prep<<<256, 256>>>(Wg, Wh, Wo, W1, W2, gk, hk);
    k_proj<<<NTILES, 128, PROJ_SMEM>>>(x, bg, bh);
    k_conv<<<dim3(Hh * Bb * Tt, 1, 2), dim3(32, 4)>>>();
    k_scan<<<(Bb * Hh * Ww * 64) / 256, 256>>>();
    k_wo<<<NTILES, 128, WO_SMEM>>>(bo, lns, lnb);
    k_mlp<<<NTILES, 256, MF_SMEM>>>(x, b1, b2, gamma, out);
}

// round 6
// speedup vs baseline: 3.3345x; 1.2081x over previous
#include <cuda_runtime.h>
#include <cuda_bf16.h>
#include <math.h>
#include <stdint.h>

#define Bb 2
#define Tt 16
#define Hh 56
#define Ww 56
#define Cc 128
#define NPTS (Bb*Tt*Hh*Ww)          /* 100352 */
#define TOT  (NPTS*Cc)              /* 12845056 */
#define HWC  (Hh*Ww*Cc)
#define KTAPS 245
#define NTILES (NPTS/128)           /* 784 */

typedef __nv_bfloat16 bf16;
typedef __nv_bfloat162 bf162;

// ---------------- device scratch (allocation-free) ----------------
__device__ __align__(16) bf16 g_gateP[TOT];
__device__ __align__(16) bf16 g_hidP[TOT];
__device__ __align__(16) bf16 g_gateS[TOT];
__device__ __align__(16) bf16 g_hidS[TOT];
__device__ __align__(16) bf16 g_E[TOT];
__device__ __align__(16) bf16 g_WgT[Cc*Cc];       // [n][k]
__device__ __align__(16) bf16 g_WhT[Cc*Cc];
__device__ __align__(16) bf16 g_WoT[Cc*Cc];
__device__ __align__(16) bf16 g_W1T[512*Cc];      // [n=512][k=128]
__device__ __align__(16) bf16 g_W2T[Cc*512];      // [n=128][k=512]
__device__ __align__(16) bf16 g_kB[2][KTAPS*Cc];  // [tap][c]

// ---------------- helpers ----------------
__device__ __forceinline__ uint32_t smem_u32(const void* p) {
    uint32_t a;
    asm("{ .reg .u64 t; cvta.to.shared.u64 t, %1; cvt.u32.u64 %0, t; }" : "=r"(a) : "l"(p));
    return a;
}
#define LDSM4(r0, r1, r2, r3, a) \
    asm volatile("ldmatrix.sync.aligned.m8n8.x4.shared.b16 {%0,%1,%2,%3}, [%4];" \
        : "=r"(r0), "=r"(r1), "=r"(r2), "=r"(r3) : "r"(a))
#define MMA16816(c, a, b) \
    asm volatile("mma.sync.aligned.m16n8k16.row.col.f32.bf16.bf16.f32 " \
        "{%0,%1,%2,%3},{%4,%5,%6,%7},{%8,%9},{%0,%1,%2,%3};" \
        : "+f"((c)[0]), "+f"((c)[1]), "+f"((c)[2]), "+f"((c)[3]) \
        : "r"((a)[0]), "r"((a)[1]), "r"((a)[2]), "r"((a)[3]), "r"((b)[0]), "r"((b)[1]))

__device__ __forceinline__ float tanh_fast(float x) {
    float y;
    asm("tanh.approx.f32 %0, %1;" : "=f"(y) : "f"(x));
    return y;
}
__device__ __forceinline__ float exp_fast(float x) {
    float y;
    asm("ex2.approx.f32 %0, %1;" : "=f"(y) : "f"(x * 1.4426950408889634f));
    return y;
}
__device__ __forceinline__ float rcp_fast(float x) {
    float y;
    asm("rcp.approx.f32 %0, %1;" : "=f"(y) : "f"(x));
    return y;
}

#define SA 136    /* smem row stride (bf16 elems) for 128-col tiles */
#define SH 520    /* smem row stride for hidden (512-col) tile */

// ---------------------------------------------------------------------------
// K0: weight prep
// ---------------------------------------------------------------------------
__global__ void k_prep(const float* __restrict__ Wg, const float* __restrict__ Wh,
                       const float* __restrict__ Wo, const float* __restrict__ W1,
                       const float* __restrict__ W2, const float* __restrict__ gk,
                       const float* __restrict__ hk) {
    int i = blockIdx.x * 256 + threadIdx.x;
    if (i < 16384) {
        int n = i >> 7, k = i & 127;
        g_WgT[i] = __float2bfloat16(Wg[k * 128 + n]);
        g_WhT[i] = __float2bfloat16(Wh[k * 128 + n]);
        g_WoT[i] = __float2bfloat16(Wo[k * 128 + n]);
    }
    if (i < 65536) {
        int n = i >> 7, k = i & 127;
        g_W1T[i] = __float2bfloat16(W1[k * 512 + n]);
        int n2 = i >> 9, k2 = i & 511;
        g_W2T[i] = __float2bfloat16(W2[k2 * 128 + n2]);
    }
    if (i < 2 * KTAPS * 128) {
        int which = i / (KTAPS * 128);
        int j = i - which * (KTAPS * 128);
        int tap = j >> 7, c = j & 127;
        const float* s = which ? hk : gk;
        g_kB[which][j] = __float2bfloat16(s[c * KTAPS + tap]);
    }
}

// ---------------------------------------------------------------------------
// K1: dual projection  [128,128] x (Wg | Wh) -> g_gateP, g_hidP (bf16)
// ---------------------------------------------------------------------------
#define PROJ_SMEM (3*128*SA*2 + 256*4)
__global__ void __launch_bounds__(128) k_proj(const float* __restrict__ x,
                                              const float* __restrict__ bg,
                                              const float* __restrict__ bh) {
    extern __shared__ __align__(16) char sm[];
    bf16* As = (bf16*)sm;
    bf16* Bs = As + 128 * SA;
    float* sbias = (float*)(Bs + 2 * 128 * SA);
    int tid = threadIdx.x, w = tid >> 5, l = tid & 31;
    size_t m0 = (size_t)blockIdx.x * 128;
    sbias[tid] = bg[tid];
    sbias[128 + tid] = bh[tid];

    const float2* xs = (const float2*)(x + m0 * 128);
    for (int idx = tid; idx < 128 * 64; idx += 128) {
        int r = idx >> 6, cp = idx & 63;
        float2 v = xs[idx];
        *(bf162*)(As + r * SA + cp * 2) = __floats2bfloat162_rn(v.x, v.y);
    }
    const uint4* wgp = (const uint4*)g_WgT;
    const uint4* whp = (const uint4*)g_WhT;
    for (int idx = tid; idx < 128 * 16; idx += 128) {
        int r = idx >> 4, c = idx & 15;
        *(uint4*)(Bs + r * SA + c * 8) = wgp[idx];
        *(uint4*)(Bs + 128 * SA + r * SA + c * 8) = whp[idx];
    }
    __syncthreads();

    int which = w >> 1;
    int wn0 = (w & 1) * 64;
    uint32_t Abase = smem_u32(As) + ((l & 15) * SA + (l >> 4) * 8) * 2;
    uint32_t Bbase = smem_u32(Bs + which * 128 * SA) + ((l & 15) * SA + (l >> 4) * 8) * 2 + wn0 * SA * 2;
    bf16* outb = which ? g_hidP : g_gateP;
    float* bb = sbias + which * 128;
    int quad = l >> 2, t4 = l & 3;

    for (int mc = 0; mc < 4; mc++) {
        float acc[2][8][4];
        #pragma unroll
        for (int mf = 0; mf < 2; mf++)
            #pragma unroll
            for (int nf = 0; nf < 8; nf++)
                #pragma unroll
                for (int e = 0; e < 4; e++) acc[mf][nf][e] = 0.f;
        #pragma unroll
        for (int k = 0; k < 8; k++) {
            uint32_t a[2][4], b[8][2];
            #pragma unroll
            for (int mf = 0; mf < 2; mf++)
                LDSM4(a[mf][0], a[mf][1], a[mf][2], a[mf][3],
                      Abase + (mc * 32 + mf * 16) * SA * 2 + k * 32);
            #pragma unroll
            for (int nf2 = 0; nf2 < 4; nf2++) {
                uint32_t r0, r1, r2, r3;
                LDSM4(r0, r1, r2, r3, Bbase + nf2 * 16 * SA * 2 + k * 32);
                b[nf2 * 2][0] = r0; b[nf2 * 2][1] = r2;
                b[nf2 * 2 + 1][0] = r1; b[nf2 * 2 + 1][1] = r3;
            }
            #pragma unroll
            for (int mf = 0; mf < 2; mf++)
                #pragma unroll
                for (int nf = 0; nf < 8; nf++) MMA16816(acc[mf][nf], a[mf], b[nf]);
        }
        #pragma unroll
        for (int mf = 0; mf < 2; mf++)
            #pragma unroll
            for (int nf = 0; nf < 8; nf++) {
                int n = wn0 + nf * 8 + t4 * 2;
                int r0 = mc * 32 + mf * 16 + quad;
                *(bf162*)(outb + (m0 + r0) * 128 + n) =
                    __floats2bfloat162_rn(acc[mf][nf][0] + bb[n], acc[mf][nf][1] + bb[n + 1]);
                *(bf162*)(outb + (m0 + r0 + 8) * 128 + n) =
                    __floats2bfloat162_rn(acc[mf][nf][2] + bb[n], acc[mf][nf][3] + bb[n + 1]);
            }
    }
}

// ---------------------------------------------------------------------------
// K2: depthwise circular conv 5x7x7, bf16 HFMA2, hoisted w-offsets
// ---------------------------------------------------------------------------
__global__ void __launch_bounds__(128) k_conv(void) {
    int ct = threadIdx.x;
    int wq = threadIdx.y;
    int which = blockIdx.z;
    const uint2* __restrict__ in = (const uint2*)(which ? g_hidP : g_gateP);
    uint2* __restrict__ outp = (uint2*)(which ? g_hidS : g_gateS);
    const uint2* __restrict__ kt = (const uint2*)g_kB[which];
    int w0 = wq * 14;
    int hbt = blockIdx.x;
    int h = hbt % Hh;
    int bt = hbt / Hh;
    int t = bt & 15;
    int bbase = bt - t;

    int offs[20];
    #pragma unroll
    for (int j = 0; j < 20; j++) {
        int wi = w0 - 3 + j;
        if (wi < 0)   wi += 56;
        if (wi >= 56) wi -= 56;
        offs[j] = wi * 32;
    }

    bf162 acc[14][2];
    bf162 z = __floats2bfloat162_rn(0.f, 0.f);
    #pragma unroll
    for (int i = 0; i < 14; i++) { acc[i][0] = z; acc[i][1] = z; }

    for (int ktp = 0; ktp < 5; ktp++) {
        int tin = (t - ktp + 18) & 15;
        int btin = bbase + tin;
        for (int kh = 0; kh < 7; kh++) {
            int hin = h - kh + 3;
            if (hin < 0)   hin += 56;
            if (hin >= 56) hin -= 56;
            const uint2* src = in + (size_t)(btin * Hh + hin) * (Ww * 32) + ct;
            uint2 win[20];
            #pragma unroll
            for (int j = 0; j < 20; j++) win[j] = src[offs[j]];
            const uint2* kb = kt + (size_t)(ktp * 49 + kh * 7) * 32 + ct;
            uint2 kv[7];
            #pragma unroll
            for (int kw = 0; kw < 7; kw++) kv[kw] = kb[(size_t)kw * 32];
            #pragma unroll
            for (int i = 0; i < 14; i++) {
                #pragma unroll
                for (int kw = 0; kw < 7; kw++) {
                    bf162 klo = *(bf162*)&kv[kw].x;
                    bf162 khi = *(bf162*)&kv[kw].y;
                    bf162 wlo = *(bf162*)&win[i + 6 - kw].x;
                    bf162 whi = *(bf162*)&win[i + 6 - kw].y;
                    acc[i][0] = __hfma2(klo, wlo, acc[i][0]);
                    acc[i][1] = __hfma2(khi, whi, acc[i][1]);
                }
            }
        }
    }
    uint2* dst = outp + ((size_t)(bt * Hh + h) * Ww + w0) * 32 + ct;
    #pragma unroll
    for (int i = 0; i < 14; i++) {
        uint2 v;
        v.x = *(uint32_t*)&acc[i][0];
        v.y = *(uint32_t*)&acc[i][1];
        dst[(size_t)i * 32] = v;
    }
}

// ---------------------------------------------------------------------------
// K3: LINEAR-domain Heinsen scan
// ---------------------------------------------------------------------------
__global__ void k_scan(void) {
    int idx = blockIdx.x * 256 + threadIdx.x;
    int cp = idx & 63;
    int rest = idx >> 6;
    int w = rest % 56; rest /= 56;
    int h = rest % 56;
    int b = rest / 56;
    size_t base = (((size_t)(b * Tt) * Hh + h) * Ww + w) * 64 + cp;
    const uint32_t* gp = (const uint32_t*)g_gateS;
    const uint32_t* hp = (const uint32_t*)g_hidS;
    uint32_t* ep = (uint32_t*)g_E;
    float H0 = 0.f, H1 = 0.f;
    #pragma unroll
    for (int t = 0; t < Tt; t++) {
        size_t off = base + (size_t)t * (HWC / 2);
        uint32_t gu = gp[off], hu = hp[off];
        float2 g2 = __bfloat1622float2(*(bf162*)&gu);
        float2 h2 = __bfloat1622float2(*(bf162*)&hu);
        float e0 = exp_fast(-fabsf(g2.x));
        float r0 = rcp_fast(1.f + e0);
        float s0 = (g2.x >= 0.f) ? r0 : e0 * r0;
        float f0 = (g2.x >= 0.f) ? e0 * r0 : r0;
        float v0 = (h2.x * h2.x + 1e-6f) * s0;
        H0 = fmaf(f0, H0, v0);
        float e1 = exp_fast(-fabsf(g2.y));
        float r1 = rcp_fast(1.f + e1);
        float s1 = (g2.y >= 0.f) ? r1 : e1 * r1;
        float f1 = (g2.y >= 0.f) ? e1 * r1 : r1;
        float v1 = (h2.y * h2.y + 1e-6f) * s1;
        H1 = fmaf(f1, H1, v1);
        bf162 o = __floats2bfloat162_rn(H0, H1);
        ep[off] = *(uint32_t*)&o;
    }
}

// ---------------------------------------------------------------------------
// K4: MEGA  E@Wo+bo -> LayerNorm(frag) -> gelu(xn@W1+b1) -> @W2+b2 -> *gm + x
// 256 threads (8 warps: wm 0..3 x wn 0..1). Single Bs weight slot with
// register prefetch (next chunk's global loads issued before current MMA).
// ---------------------------------------------------------------------------
#define WM_SMEM (128*SA*2 + 128*SA*2 + 128*SH*2 + 1152*4 + 512*4 + 256*4)
__global__ void __launch_bounds__(256) k_womlp(const float* __restrict__ x,
                                               const float* __restrict__ bo,
                                               const float* __restrict__ lns,
                                               const float* __restrict__ lnb,
                                               const float* __restrict__ b1,
                                               const float* __restrict__ b2,
                                               const float* __restrict__ gamma,
                                               float* __restrict__ out) {
    extern __shared__ __align__(16) char sm[];
    bf16* As = (bf16*)sm;                   // 128 x SA : E tile, then xn tile
    bf16* Bs = As + 128 * SA;               // 128 x SA : weight chunk slot
    bf16* Hs = Bs + 128 * SA;               // 128 x SH : hidden
    float* sbo  = (float*)(Hs + 128 * SH);  // 128
    float* slns = sbo + 128;                // 128
    float* slnb = slns + 128;               // 128
    float* sb1  = slnb + 128;               // 512
    float* sb2  = sb1 + 512;                // 128
    float* sgm  = sb2 + 128;                // 128
    float* rs   = sgm + 128;                // 128*2 row sums
    float* rq   = rs + 256;                 // 128*2 row sumsq
    float2* stat = (float2*)(rq + 256);     // 128 (mean, rstd)

    int tid = threadIdx.x, w = tid >> 5, l = tid & 31;
    int wm = w >> 1, wn = w & 1;
    int quad = l >> 2, t4 = l & 3;
    size_t m0 = (size_t)blockIdx.x * 128;

    if (tid < 128) {
        sbo[tid] = bo[tid]; slns[tid] = lns[tid]; slnb[tid] = lnb[tid];
        sb2[tid] = b2[tid]; sgm[tid] = gamma[tid];
    }
    sb1[tid] = b1[tid]; sb1[256 + tid] = b1[256 + tid];

    // load E tile + Wo chunk
    const uint4* ep = (const uint4*)(g_E + m0 * 128);
    for (int j = 0; j < 8; j++) {
        int i = tid + 256 * j;
        int r = i >> 4, c = i & 15;
        *(uint4*)(As + r * SA + c * 8) = ep[i];
    }
    {
        const uint4* wop = (const uint4*)g_WoT;
        uint4 pf[8];
        #pragma unroll
        for (int j = 0; j < 8; j++) pf[j] = wop[tid + 256 * j];
        #pragma unroll
        for (int j = 0; j < 8; j++) {
            int i = tid + 256 * j;
            int r = i >> 4, c = i & 15;
            *(uint4*)(Bs + r * SA + c * 8) = pf[j];
        }
    }
    __syncthreads();

    uint32_t Abase = smem_u32(As) + ((l & 15) * SA + (l >> 4) * 8) * 2 + (wm * 32) * SA * 2;
    uint32_t Bbase = smem_u32(Bs) + ((l & 15) * SA + (l >> 4) * 8) * 2 + (wn * 64) * SA * 2;
    uint32_t Hbase = smem_u32(Hs) + ((l & 15) * SH + (l >> 4) * 8) * 2 + (wm * 32) * SH * 2;

    const uint4* w1p = (const uint4*)g_W1T;
    const uint4* w2p = (const uint4*)g_W2T;
    uint4 pf[8];

    // ---------------- stage 0: wo GEMM (acc over full K=128) ----------------
    // prefetch W1 chunk 0 while MMA runs
    #pragma unroll
    for (int j = 0; j < 8; j++) pf[j] = w1p[tid + 256 * j];

    float acc[2][8][4];
    #pragma unroll
    for (int mf = 0; mf < 2; mf++)
        #pragma unroll
        for (int nf = 0; nf < 8; nf++)
            #pragma unroll
            for (int e = 0; e < 4; e++) acc[mf][nf][e] = 0.f;
    #pragma unroll
    for (int k = 0; k < 8; k++) {
        uint32_t a[2][4], b[8][2];
        #pragma unroll
        for (int mf = 0; mf < 2; mf++)
            LDSM4(a[mf][0], a[mf][1], a[mf][2], a[mf][3],
                  Abase + mf * 16 * SA * 2 + k * 32);
        #pragma unroll
        for (int nf2 = 0; nf2 < 4; nf2++) {
            uint32_t r0, r1, r2, r3;
            LDSM4(r0, r1, r2, r3, Bbase + nf2 * 16 * SA * 2 + k * 32);
            b[nf2 * 2][0] = r0; b[nf2 * 2][1] = r2;
            b[nf2 * 2 + 1][0] = r1; b[nf2 * 2 + 1][1] = r3;
        }
        #pragma unroll
        for (int mf = 0; mf < 2; mf++)
            #pragma unroll
            for (int nf = 0; nf < 8; nf++) MMA16816(acc[mf][nf], a[mf], b[nf]);
    }

    // add bias, per-row partial sums (this warp's 64-col half)
    #pragma unroll
    for (int mf = 0; mf < 2; mf++) {
        float s0 = 0.f, q0 = 0.f, s1 = 0.f, q1 = 0.f;
        #pragma unroll
        for (int nf = 0; nf < 8; nf++) {
            int n = wn * 64 + nf * 8 + t4 * 2;
            float v0 = acc[mf][nf][0] + sbo[n];
            float v1 = acc[mf][nf][1] + sbo[n + 1];
            float v2 = acc[mf][nf][2] + sbo[n];
            float v3 = acc[mf][nf][3] + sbo[n + 1];
            acc[mf][nf][0] = v0; acc[mf][nf][1] = v1;
            acc[mf][nf][2] = v2; acc[mf][nf][3] = v3;
            s0 += v0 + v1; q0 += v0 * v0 + v1 * v1;
            s1 += v2 + v3; q1 += v2 * v2 + v3 * v3;
        }
        #pragma unroll
        for (int o = 1; o < 4; o <<= 1) {
            s0 += __shfl_xor_sync(0xffffffffu, s0, o);
            q0 += __shfl_xor_sync(0xffffffffu, q0, o);
            s1 += __shfl_xor_sync(0xffffffffu, s1, o);
            q1 += __shfl_xor_sync(0xffffffffu, q1, o);
        }
        if (t4 == 0) {
            int rA = wm * 32 + mf * 16 + quad;
            rs[rA * 2 + wn] = s0; rq[rA * 2 + wn] = q0;
            rs[(rA + 8) * 2 + wn] = s1; rq[(rA + 8) * 2 + wn] = q1;
        }
    }
    __syncthreads();            // MMA smem reads done + rs/rq visible

    // store W1c0, compute LN stats
    #pragma unroll
    for (int j = 0; j < 8; j++) {
        int i = tid + 256 * j;
        int r = i >> 4, c = i & 15;
        *(uint4*)(Bs + r * SA + c * 8) = pf[j];
    }
    if (tid < 128) {
        float mean = (rs[tid * 2] + rs[tid * 2 + 1]) * (1.f / 128.f);
        float var = (rq[tid * 2] + rq[tid * 2 + 1]) * (1.f / 128.f) - mean * mean;
        stat[tid] = make_float2(mean, rsqrtf(var + 1e-6f));
    }
    __syncthreads();            // stats + Bs visible

    // write xn (bf16) into As
    #pragma unroll
    for (int mf = 0; mf < 2; mf++) {
        int rA = wm * 32 + mf * 16 + quad;
        float2 stA = stat[rA], stB = stat[rA + 8];
        #pragma unroll
        for (int nf = 0; nf < 8; nf++) {
            int n = wn * 64 + nf * 8 + t4 * 2;
            float x0 = (acc[mf][nf][0] - stA.x) * stA.y * slns[n] + slnb[n];
            float x1 = (acc[mf][nf][1] - stA.x) * stA.y * slns[n + 1] + slnb[n + 1];
            float x2 = (acc[mf][nf][2] - stB.x) * stB.y * slns[n] + slnb[n];
            float x3 = (acc[mf][nf][3] - stB.x) * stB.y * slns[n + 1] + slnb[n + 1];
            *(bf162*)(As + rA * SA + n) = __floats2bfloat162_rn(x0, x1);
            *(bf162*)(As + (rA + 8) * SA + n) = __floats2bfloat162_rn(x2, x3);
        }
    }
    __syncthreads();            // xn visible

    // ---------------- stage 1: hidden = gelu(xn @ W1 + b1) ----------------
    for (int nc = 0; nc < 4; nc++) {
        // prefetch next chunk (W1 nc+1, or W2 kc=0 when nc==3)
        #pragma unroll
        for (int j = 0; j < 8; j++) {
            int i = tid + 256 * j;
            if (nc < 3) pf[j] = w1p[(nc + 1) * 2048 + i];
            else        pf[j] = w2p[(i >> 4) * 64 + (i & 15)];
        }
        float a1[2][8][4];
        #pragma unroll
        for (int mf = 0; mf < 2; mf++)
            #pragma unroll
            for (int nf = 0; nf < 8; nf++)
                #pragma unroll
                for (int e = 0; e < 4; e++) a1[mf][nf][e] = 0.f;
        #pragma unroll
        for (int k = 0; k < 8; k++) {
            uint32_t a[2][4], b[8][2];
            #pragma unroll
            for (int mf = 0; mf < 2; mf++)
                LDSM4(a[mf][0], a[mf][1], a[mf][2], a[mf][3],
                      Abase + mf * 16 * SA * 2 + k * 32);
            #pragma unroll
            for (int nf2 = 0; nf2 < 4; nf2++) {
                uint32_t r0, r1, r2, r3;
                LDSM4(r0, r1, r2, r3, Bbase + nf2 * 16 * SA * 2 + k * 32);
                b[nf2 * 2][0] = r0; b[nf2 * 2][1] = r2;
                b[nf2 * 2 + 1][0] = r1; b[nf2 * 2 + 1][1] = r3;
            }
            #pragma unroll
            for (int mf = 0; mf < 2; mf++)
                #pragma unroll
                for (int nf = 0; nf < 8; nf++) MMA16816(a1[mf][nf], a[mf], b[nf]);
        }
        #pragma unroll
        for (int mf = 0; mf < 2; mf++)
            #pragma unroll
            for (int nf = 0; nf < 8; nf++) {
                int nl = wn * 64 + nf * 8 + t4 * 2;
                int ng = nc * 128 + nl;
                int r0 = wm * 32 + mf * 16 + quad;
                #pragma unroll
                for (int hrow = 0; hrow < 2; hrow++) {
                    float v0 = a1[mf][nf][hrow * 2] + sb1[ng];
                    float v1 = a1[mf][nf][hrow * 2 + 1] + sb1[ng + 1];
                    float t0 = tanh_fast(0.7978845608028654f * (v0 + 0.044715f * v0 * v0 * v0));
                    float t1 = tanh_fast(0.7978845608028654f * (v1 + 0.044715f * v1 * v1 * v1));
                    *(bf162*)(Hs + (r0 + hrow * 8) * SH + ng) =
                        __floats2bfloat162_rn(0.5f * v0 * (1.f + t0), 0.5f * v1 * (1.f + t1));
                }
            }
        __syncthreads();        // Bs reads done
        #pragma unroll
        for (int j = 0; j < 8; j++) {
            int i = tid + 256 * j;
            int r = i >> 4, c = i & 15;
            *(uint4*)(Bs + r * SA + c * 8) = pf[j];
        }
        __syncthreads();        // new chunk + (last iter) Hs visible
    }

    // ---------------- stage 2: y = hidden @ W2 (K=512, 4 chunks) ----------------
    float acc2[2][8][4];
    #pragma unroll
    for (int mf = 0; mf < 2; mf++)
        #pragma unroll
        for (int nf = 0; nf < 8; nf++)
            #pragma unroll
            for (int e = 0; e < 4; e++) acc2[mf][nf][e] = 0.f;

    for (int kc = 0; kc < 4; kc++) {
        if (kc < 3) {
            #pragma unroll
            for (int j = 0; j < 8; j++) {
                int i = tid + 256 * j;
                pf[j] = w2p[(size_t)(i >> 4) * 64 + (kc + 1) * 16 + (i & 15)];
            }
        }
        #pragma unroll
        for (int k = 0; k < 8; k++) {
            uint32_t a[2][4], b[8][2];
            #pragma unroll
            for (int mf = 0; mf < 2; mf++)
                LDSM4(a[mf][0], a[mf][1], a[mf][2], a[mf][3],
                      Hbase + mf * 16 * SH * 2 + kc * 256 + k * 32);
            #pragma unroll
            for (int nf2 = 0; nf2 < 4; nf2++) {
                uint32_t r0, r1, r2, r3;
                LDSM4(r0, r1, r2, r3, Bbase + nf2 * 16 * SA * 2 + k * 32);
                b[nf2 * 2][0] = r0; b[nf2 * 2][1] = r2;
                b[nf2 * 2 + 1][0] = r1; b[nf2 * 2 + 1][1] = r3;
            }
            #pragma unroll
            for (int mf = 0; mf < 2; mf++)
                #pragma unroll
                for (int nf = 0; nf < 8; nf++) MMA16816(acc2[mf][nf], a[mf], b[nf]);
        }
        if (kc < 3) {
            __syncthreads();
            #pragma unroll
            for (int j = 0; j < 8; j++) {
                int i = tid + 256 * j;
                int r = i >> 4, c = i & 15;
                *(uint4*)(Bs + r * SA + c * 8) = pf[j];
            }
            __syncthreads();
        }
    }

    // ---------------- epilogue: *gamma + residual -> out (f32) ----------------
    #pragma unroll
    for (int mf = 0; mf < 2; mf++)
        #pragma unroll
        for (int nf = 0; nf < 8; nf++) {
            int n = wn * 64 + nf * 8 + t4 * 2;
            size_t r0 = m0 + wm * 32 + mf * 16 + quad;
            #pragma unroll
            for (int hrow = 0; hrow < 2; hrow++) {
                size_t r = r0 + hrow * 8;
                float v0 = (acc2[mf][nf][hrow * 2] + sb2[n]) * sgm[n] + x[r * 128 + n];
                float v1 = (acc2[mf][nf][hrow * 2 + 1] + sb2[n + 1]) * sgm[n + 1] + x[r * 128 + n + 1];
                out[r * 128 + n] = v0;
                out[r * 128 + n + 1] = v1;
            }
        }
}

// ---------------------------------------------------------------------------
extern "C" void kernel_launch(void* const* d_in, const int* in_sizes, int n_in,
                              void* d_out, int out_size) {
    const float* x     = (const float*)d_in[0];
    const float* Wg    = (const float*)d_in[1];
    const float* bg    = (const float*)d_in[2];
    const float* Wh    = (const float*)d_in[3];
    const float* bh    = (const float*)d_in[4];
    const float* gk    = (const float*)d_in[5];
    const float* hk    = (const float*)d_in[6];
    const float* Wo    = (const float*)d_in[7];
    const float* bo    = (const float*)d_in[8];
    const float* lns   = (const float*)d_in[9];
    const float* lnb   = (const float*)d_in[10];
    const float* W1    = (const float*)d_in[11];
    const float* b1    = (const float*)d_in[12];
    const float* W2    = (const float*)d_in[13];
    const float* b2    = (const float*)d_in[14];
    const float* gamma = (const float*)d_in[15];
    float* out = (float*)d_out;

    cudaFuncSetAttribute(k_proj,  cudaFuncAttributeMaxDynamicSharedMemorySize, PROJ_SMEM);
    cudaFuncSetAttribute(k_womlp, cudaFuncAttributeMaxDynamicSharedMemorySize, WM_SMEM);

    k_prep<<<256, 256>>>(Wg, Wh, Wo, W1, W2, gk, hk);
    k_proj<<<NTILES, 128, PROJ_SMEM>>>(x, bg, bh);
    k_conv<<<dim3(Hh * Bb * Tt, 1, 2), dim3(32, 4)>>>();
    k_scan<<<(Bb * Hh * Ww * 64) / 256, 256>>>();
    k_womlp<<<NTILES, 256, WM_SMEM>>>(x, bo, lns, lnb, b1, b2, gamma, out);
}

// round 7
// speedup vs baseline: 3.3764x; 1.0126x over previous
#include <cuda_runtime.h>
#include <cuda_bf16.h>
#include <math.h>
#include <stdint.h>

#define Bb 2
#define Tt 16
#define Hh 56
#define Ww 56
#define Cc 128
#define NPTS (Bb*Tt*Hh*Ww)          /* 100352 */
#define TOT  (NPTS*Cc)              /* 12845056 */
#define HWC  (Hh*Ww*Cc)
#define KTAPS 245
#define NTILES (NPTS/128)           /* 784 */

typedef __nv_bfloat16 bf16;
typedef __nv_bfloat162 bf162;

// ---------------- device scratch (allocation-free) ----------------
__device__ __align__(16) bf16 g_gateP[TOT];
__device__ __align__(16) bf16 g_hidP[TOT];
__device__ __align__(16) bf16 g_gateS[TOT];
__device__ __align__(16) bf16 g_hidS[TOT];
__device__ __align__(16) bf16 g_E[TOT];
__device__ __align__(16) bf16 g_WgT[Cc*Cc];       // [n][k]
__device__ __align__(16) bf16 g_WhT[Cc*Cc];
__device__ __align__(16) bf16 g_WoT[Cc*Cc];
__device__ __align__(16) bf16 g_W1T[512*Cc];      // [n=512][k=128]
__device__ __align__(16) bf16 g_W2T[Cc*512];      // [n=128][k=512]
__device__ __align__(16) bf16 g_kB[2][KTAPS*Cc];  // [tap][c]

// ---------------- helpers ----------------
__device__ __forceinline__ uint32_t smem_u32(const void* p) {
    uint32_t a;
    asm("{ .reg .u64 t; cvta.to.shared.u64 t, %1; cvt.u32.u64 %0, t; }" : "=r"(a) : "l"(p));
    return a;
}
#define LDSM4(r0, r1, r2, r3, a) \
    asm volatile("ldmatrix.sync.aligned.m8n8.x4.shared.b16 {%0,%1,%2,%3}, [%4];" \
        : "=r"(r0), "=r"(r1), "=r"(r2), "=r"(r3) : "r"(a))
#define MMA16816(c, a, b) \
    asm volatile("mma.sync.aligned.m16n8k16.row.col.f32.bf16.bf16.f32 " \
        "{%0,%1,%2,%3},{%4,%5,%6,%7},{%8,%9},{%0,%1,%2,%3};" \
        : "+f"((c)[0]), "+f"((c)[1]), "+f"((c)[2]), "+f"((c)[3]) \
        : "r"((a)[0]), "r"((a)[1]), "r"((a)[2]), "r"((a)[3]), "r"((b)[0]), "r"((b)[1]))

__device__ __forceinline__ float tanh_fast(float x) {
    float y;
    asm("tanh.approx.f32 %0, %1;" : "=f"(y) : "f"(x));
    return y;
}
__device__ __forceinline__ float exp_fast(float x) {
    float y;
    asm("ex2.approx.f32 %0, %1;" : "=f"(y) : "f"(x * 1.4426950408889634f));
    return y;
}
__device__ __forceinline__ float rcp_fast(float x) {
    float y;
    asm("rcp.approx.f32 %0, %1;" : "=f"(y) : "f"(x));
    return y;
}

#define SA 136    /* smem row stride (bf16 elems) for 128-col tiles */
#define SH 520    /* smem row stride for hidden (512-col) tile */

// ---------------------------------------------------------------------------
// K0: weight prep
// ---------------------------------------------------------------------------
__global__ void k_prep(const float* __restrict__ Wg, const float* __restrict__ Wh,
                       const float* __restrict__ Wo, const float* __restrict__ W1,
                       const float* __restrict__ W2, const float* __restrict__ gk,
                       const float* __restrict__ hk) {
    int i = blockIdx.x * 256 + threadIdx.x;
    if (i < 16384) {
        int n = i >> 7, k = i & 127;
        g_WgT[i] = __float2bfloat16(Wg[k * 128 + n]);
        g_WhT[i] = __float2bfloat16(Wh[k * 128 + n]);
        g_WoT[i] = __float2bfloat16(Wo[k * 128 + n]);
    }
    if (i < 65536) {
        int n = i >> 7, k = i & 127;
        g_W1T[i] = __float2bfloat16(W1[k * 512 + n]);
        int n2 = i >> 9, k2 = i & 511;
        g_W2T[i] = __float2bfloat16(W2[k2 * 128 + n2]);
    }
    if (i < 2 * KTAPS * 128) {
        int which = i / (KTAPS * 128);
        int j = i - which * (KTAPS * 128);
        int tap = j >> 7, c = j & 127;
        const float* s = which ? hk : gk;
        g_kB[which][j] = __float2bfloat16(s[c * KTAPS + tap]);
    }
}

// ---------------------------------------------------------------------------
// K1: dual projection  [128,128] x (Wg | Wh) -> g_gateP, g_hidP (bf16)
// ---------------------------------------------------------------------------
#define PROJ_SMEM (3*128*SA*2 + 256*4)
__global__ void __launch_bounds__(128) k_proj(const float* __restrict__ x,
                                              const float* __restrict__ bg,
                                              const float* __restrict__ bh) {
    extern __shared__ __align__(16) char sm[];
    bf16* As = (bf16*)sm;
    bf16* Bs = As + 128 * SA;
    float* sbias = (float*)(Bs + 2 * 128 * SA);
    int tid = threadIdx.x, w = tid >> 5, l = tid & 31;
    size_t m0 = (size_t)blockIdx.x * 128;
    sbias[tid] = bg[tid];
    sbias[128 + tid] = bh[tid];

    const float2* xs = (const float2*)(x + m0 * 128);
    for (int idx = tid; idx < 128 * 64; idx += 128) {
        int r = idx >> 6, cp = idx & 63;
        float2 v = xs[idx];
        *(bf162*)(As + r * SA + cp * 2) = __floats2bfloat162_rn(v.x, v.y);
    }
    const uint4* wgp = (const uint4*)g_WgT;
    const uint4* whp = (const uint4*)g_WhT;
    for (int idx = tid; idx < 128 * 16; idx += 128) {
        int r = idx >> 4, c = idx & 15;
        *(uint4*)(Bs + r * SA + c * 8) = wgp[idx];
        *(uint4*)(Bs + 128 * SA + r * SA + c * 8) = whp[idx];
    }
    __syncthreads();

    int which = w >> 1;
    int wn0 = (w & 1) * 64;
    uint32_t Abase = smem_u32(As) + ((l & 15) * SA + (l >> 4) * 8) * 2;
    uint32_t Bbase = smem_u32(Bs + which * 128 * SA) + ((l & 15) * SA + (l >> 4) * 8) * 2 + wn0 * SA * 2;
    bf16* outb = which ? g_hidP : g_gateP;
    float* bb = sbias + which * 128;
    int quad = l >> 2, t4 = l & 3;

    for (int mc = 0; mc < 4; mc++) {
        float acc[2][8][4];
        #pragma unroll
        for (int mf = 0; mf < 2; mf++)
            #pragma unroll
            for (int nf = 0; nf < 8; nf++)
                #pragma unroll
                for (int e = 0; e < 4; e++) acc[mf][nf][e] = 0.f;
        #pragma unroll
        for (int k = 0; k < 8; k++) {
            uint32_t a[2][4], b[8][2];
            #pragma unroll
            for (int mf = 0; mf < 2; mf++)
                LDSM4(a[mf][0], a[mf][1], a[mf][2], a[mf][3],
                      Abase + (mc * 32 + mf * 16) * SA * 2 + k * 32);
            #pragma unroll
            for (int nf2 = 0; nf2 < 4; nf2++) {
                uint32_t r0, r1, r2, r3;
                LDSM4(r0, r1, r2, r3, Bbase + nf2 * 16 * SA * 2 + k * 32);
                b[nf2 * 2][0] = r0; b[nf2 * 2][1] = r2;
                b[nf2 * 2 + 1][0] = r1; b[nf2 * 2 + 1][1] = r3;
            }
            #pragma unroll
            for (int mf = 0; mf < 2; mf++)
                #pragma unroll
                for (int nf = 0; nf < 8; nf++) MMA16816(acc[mf][nf], a[mf], b[nf]);
        }
        #pragma unroll
        for (int mf = 0; mf < 2; mf++)
            #pragma unroll
            for (int nf = 0; nf < 8; nf++) {
                int n = wn0 + nf * 8 + t4 * 2;
                int r0 = mc * 32 + mf * 16 + quad;
                *(bf162*)(outb + (m0 + r0) * 128 + n) =
                    __floats2bfloat162_rn(acc[mf][nf][0] + bb[n], acc[mf][nf][1] + bb[n + 1]);
                *(bf162*)(outb + (m0 + r0 + 8) * 128 + n) =
                    __floats2bfloat162_rn(acc[mf][nf][2] + bb[n], acc[mf][nf][3] + bb[n + 1]);
            }
    }
}

// ---------------------------------------------------------------------------
// K2: depthwise circular conv 5x7x7 with t-reuse.
// Block: 256 threads = 64 channel-pairs x 4 t-groups (4 t each).
// Each thread: 4 t-outputs x 14 w x 2 ch. Input rows loaded once per
// (kh, t_in) and consumed by all valid kt taps (compile-time dispatch).
// ---------------------------------------------------------------------------
__global__ void __launch_bounds__(256) k_conv(void) {
    int ct = threadIdx.x & 63;        // channel pair 0..63
    int tq = threadIdx.x >> 6;        // t-group 0..3
    int which = blockIdx.z;
    const uint32_t* __restrict__ in = (const uint32_t*)(which ? g_hidP : g_gateP);
    uint32_t* __restrict__ outp = (uint32_t*)(which ? g_hidS : g_gateS);
    const uint32_t* __restrict__ kt = (const uint32_t*)g_kB[which];
    int w0 = blockIdx.x * 14;
    int by = blockIdx.y;              // b*Hh + h
    int h = by % Hh;
    int b = by / Hh;
    int t0 = tq * 4;

    int offs[20];
    #pragma unroll
    for (int j = 0; j < 20; j++) {
        int wi = w0 - 3 + j;
        if (wi < 0)   wi += 56;
        if (wi >= 56) wi -= 56;
        offs[j] = wi * 64;
    }

    bf162 acc[4][14];
    bf162 z = __floats2bfloat162_rn(0.f, 0.f);
    #pragma unroll
    for (int tr = 0; tr < 4; tr++)
        #pragma unroll
        for (int i = 0; i < 14; i++) acc[tr][i] = z;

    for (int kh = 0; kh < 7; kh++) {
        int hin = h - kh + 3;
        if (hin < 0)   hin += 56;
        if (hin >= 56) hin -= 56;
        // kernel taps for this kh: all 5 kt x 7 kw
        uint32_t kv[5][7];
        #pragma unroll
        for (int ktp = 0; ktp < 5; ktp++)
            #pragma unroll
            for (int kw = 0; kw < 7; kw++)
                kv[ktp][kw] = kt[(size_t)(ktp * 49 + kh * 7 + kw) * 64 + ct];

        #pragma unroll
        for (int j = 0; j < 8; j++) {
            int t_in = (t0 - 2 + j) & 15;
            const uint32_t* src = in + (size_t)((b * 16 + t_in) * Hh + hin) * (Ww * 64) + ct;
            uint32_t win[20];
            #pragma unroll
            for (int jj = 0; jj < 20; jj++) win[jj] = src[offs[jj]];
            #pragma unroll
            for (int ktp = 0; ktp < 5; ktp++) {
                int tr = j + ktp - 4;
                if (tr >= 0 && tr < 4) {
                    #pragma unroll
                    for (int i = 0; i < 14; i++) {
                        #pragma unroll
                        for (int kw = 0; kw < 7; kw++)
                            acc[tr][i] = __hfma2(*(bf162*)&kv[ktp][kw],
                                                 *(bf162*)&win[i + 6 - kw],
                                                 acc[tr][i]);
                    }
                }
            }
        }
    }
    #pragma unroll
    for (int tr = 0; tr < 4; tr++) {
        uint32_t* dst = outp + (size_t)(((b * 16 + t0 + tr) * Hh + h) * Ww + w0) * 64 + ct;
        #pragma unroll
        for (int i = 0; i < 14; i++)
            dst[(size_t)i * 64] = *(uint32_t*)&acc[tr][i];
    }
}

// ---------------------------------------------------------------------------
// K3: LINEAR-domain Heinsen scan
// ---------------------------------------------------------------------------
__global__ void k_scan(void) {
    int idx = blockIdx.x * 256 + threadIdx.x;
    int cp = idx & 63;
    int rest = idx >> 6;
    int w = rest % 56; rest /= 56;
    int h = rest % 56;
    int b = rest / 56;
    size_t base = (((size_t)(b * Tt) * Hh + h) * Ww + w) * 64 + cp;
    const uint32_t* gp = (const uint32_t*)g_gateS;
    const uint32_t* hp = (const uint32_t*)g_hidS;
    uint32_t* ep = (uint32_t*)g_E;
    float H0 = 0.f, H1 = 0.f;
    #pragma unroll
    for (int t = 0; t < Tt; t++) {
        size_t off = base + (size_t)t * (HWC / 2);
        uint32_t gu = gp[off], hu = hp[off];
        float2 g2 = __bfloat1622float2(*(bf162*)&gu);
        float2 h2 = __bfloat1622float2(*(bf162*)&hu);
        float e0 = exp_fast(-fabsf(g2.x));
        float r0 = rcp_fast(1.f + e0);
        float s0 = (g2.x >= 0.f) ? r0 : e0 * r0;
        float f0 = (g2.x >= 0.f) ? e0 * r0 : r0;
        float v0 = (h2.x * h2.x + 1e-6f) * s0;
        H0 = fmaf(f0, H0, v0);
        float e1 = exp_fast(-fabsf(g2.y));
        float r1 = rcp_fast(1.f + e1);
        float s1 = (g2.y >= 0.f) ? r1 : e1 * r1;
        float f1 = (g2.y >= 0.f) ? e1 * r1 : r1;
        float v1 = (h2.y * h2.y + 1e-6f) * s1;
        H1 = fmaf(f1, H1, v1);
        bf162 o = __floats2bfloat162_rn(H0, H1);
        ep[off] = *(uint32_t*)&o;
    }
}

// ---------------------------------------------------------------------------
// K4: MEGA  E@Wo+bo -> LayerNorm(frag) -> gelu(xn@W1+b1) -> @W2+b2 -> *gm + x
// ---------------------------------------------------------------------------
#define WM_SMEM (128*SA*2 + 128*SA*2 + 128*SH*2 + 1152*4 + 512*4 + 256*4)
__global__ void __launch_bounds__(256) k_womlp(const float* __restrict__ x,
                                               const float* __restrict__ bo,
                                               const float* __restrict__ lns,
                                               const float* __restrict__ lnb,
                                               const float* __restrict__ b1,
                                               const float* __restrict__ b2,
                                               const float* __restrict__ gamma,
                                               float* __restrict__ out) {
    extern __shared__ __align__(16) char sm[];
    bf16* As = (bf16*)sm;
    bf16* Bs = As + 128 * SA;
    bf16* Hs = Bs + 128 * SA;
    float* sbo  = (float*)(Hs + 128 * SH);
    float* slns = sbo + 128;
    float* slnb = slns + 128;
    float* sb1  = slnb + 128;
    float* sb2  = sb1 + 512;
    float* sgm  = sb2 + 128;
    float* rs   = sgm + 128;
    float* rq   = rs + 256;
    float2* stat = (float2*)(rq + 256);

    int tid = threadIdx.x, w = tid >> 5, l = tid & 31;
    int wm = w >> 1, wn = w & 1;
    int quad = l >> 2, t4 = l & 3;
    size_t m0 = (size_t)blockIdx.x * 128;

    if (tid < 128) {
        sbo[tid] = bo[tid]; slns[tid] = lns[tid]; slnb[tid] = lnb[tid];
        sb2[tid] = b2[tid]; sgm[tid] = gamma[tid];
    }
    sb1[tid] = b1[tid]; sb1[256 + tid] = b1[256 + tid];

    const uint4* ep = (const uint4*)(g_E + m0 * 128);
    for (int j = 0; j < 8; j++) {
        int i = tid + 256 * j;
        int r = i >> 4, c = i & 15;
        *(uint4*)(As + r * SA + c * 8) = ep[i];
    }
    {
        const uint4* wop = (const uint4*)g_WoT;
        uint4 pf0[8];
        #pragma unroll
        for (int j = 0; j < 8; j++) pf0[j] = wop[tid + 256 * j];
        #pragma unroll
        for (int j = 0; j < 8; j++) {
            int i = tid + 256 * j;
            int r = i >> 4, c = i & 15;
            *(uint4*)(Bs + r * SA + c * 8) = pf0[j];
        }
    }
    __syncthreads();

    uint32_t Abase = smem_u32(As) + ((l & 15) * SA + (l >> 4) * 8) * 2 + (wm * 32) * SA * 2;
    uint32_t Bbase = smem_u32(Bs) + ((l & 15) * SA + (l >> 4) * 8) * 2 + (wn * 64) * SA * 2;
    uint32_t Hbase = smem_u32(Hs) + ((l & 15) * SH + (l >> 4) * 8) * 2 + (wm * 32) * SH * 2;

    const uint4* w1p = (const uint4*)g_W1T;
    const uint4* w2p = (const uint4*)g_W2T;
    uint4 pf[8];

    // ---------------- stage 0: wo GEMM ----------------
    #pragma unroll
    for (int j = 0; j < 8; j++) pf[j] = w1p[tid + 256 * j];

    float acc[2][8][4];
    #pragma unroll
    for (int mf = 0; mf < 2; mf++)
        #pragma unroll
        for (int nf = 0; nf < 8; nf++)
            #pragma unroll
            for (int e = 0; e < 4; e++) acc[mf][nf][e] = 0.f;
    #pragma unroll
    for (int k = 0; k < 8; k++) {
        uint32_t a[2][4], b[8][2];
        #pragma unroll
        for (int mf = 0; mf < 2; mf++)
            LDSM4(a[mf][0], a[mf][1], a[mf][2], a[mf][3],
                  Abase + mf * 16 * SA * 2 + k * 32);
        #pragma unroll
        for (int nf2 = 0; nf2 < 4; nf2++) {
            uint32_t r0, r1, r2, r3;
            LDSM4(r0, r1, r2, r3, Bbase + nf2 * 16 * SA * 2 + k * 32);
            b[nf2 * 2][0] = r0; b[nf2 * 2][1] = r2;
            b[nf2 * 2 + 1][0] = r1; b[nf2 * 2 + 1][1] = r3;
        }
        #pragma unroll
        for (int mf = 0; mf < 2; mf++)
            #pragma unroll
            for (int nf = 0; nf < 8; nf++) MMA16816(acc[mf][nf], a[mf], b[nf]);
    }

    #pragma unroll
    for (int mf = 0; mf < 2; mf++) {
        float s0 = 0.f, q0 = 0.f, s1 = 0.f, q1 = 0.f;
        #pragma unroll
        for (int nf = 0; nf < 8; nf++) {
            int n = wn * 64 + nf * 8 + t4 * 2;
            float v0 = acc[mf][nf][0] + sbo[n];
            float v1 = acc[mf][nf][1] + sbo[n + 1];
            float v2 = acc[mf][nf][2] + sbo[n];
            float v3 = acc[mf][nf][3] + sbo[n + 1];
            acc[mf][nf][0] = v0; acc[mf][nf][1] = v1;
            acc[mf][nf][2] = v2; acc[mf][nf][3] = v3;
            s0 += v0 + v1; q0 += v0 * v0 + v1 * v1;
            s1 += v2 + v3; q1 += v2 * v2 + v3 * v3;
        }
        #pragma unroll
        for (int o = 1; o < 4; o <<= 1) {
            s0 += __shfl_xor_sync(0xffffffffu, s0, o);
            q0 += __shfl_xor_sync(0xffffffffu, q0, o);
            s1 += __shfl_xor_sync(0xffffffffu, s1, o);
            q1 += __shfl_xor_sync(0xffffffffu, q1, o);
        }
        if (t4 == 0) {
            int rA = wm * 32 + mf * 16 + quad;
            rs[rA * 2 + wn] = s0; rq[rA * 2 + wn] = q0;
            rs[(rA + 8) * 2 + wn] = s1; rq[(rA + 8) * 2 + wn] = q1;
        }
    }
    __syncthreads();

    #pragma unroll
    for (int j = 0; j < 8; j++) {
        int i = tid + 256 * j;
        int r = i >> 4, c = i & 15;
        *(uint4*)(Bs + r * SA + c * 8) = pf[j];
    }
    if (tid < 128) {
        float mean = (rs[tid * 2] + rs[tid * 2 + 1]) * (1.f / 128.f);
        float var = (rq[tid * 2] + rq[tid * 2 + 1]) * (1.f / 128.f) - mean * mean;
        stat[tid] = make_float2(mean, rsqrtf(var + 1e-6f));
    }
    __syncthreads();

    #pragma unroll
    for (int mf = 0; mf < 2; mf++) {
        int rA = wm * 32 + mf * 16 + quad;
        float2 stA = stat[rA], stB = stat[rA + 8];
        #pragma unroll
        for (int nf = 0; nf < 8; nf++) {
            int n = wn * 64 + nf * 8 + t4 * 2;
            float x0 = (acc[mf][nf][0] - stA.x) * stA.y * slns[n] + slnb[n];
            float x1 = (acc[mf][nf][1] - stA.x) * stA.y * slns[n + 1] + slnb[n + 1];
            float x2 = (acc[mf][nf][2] - stB.x) * stB.y * slns[n] + slnb[n];
            float x3 = (acc[mf][nf][3] - stB.x) * stB.y * slns[n + 1] + slnb[n + 1];
            *(bf162*)(As + rA * SA + n) = __floats2bfloat162_rn(x0, x1);
            *(bf162*)(As + (rA + 8) * SA + n) = __floats2bfloat162_rn(x2, x3);
        }
    }
    __syncthreads();

    // ---------------- stage 1: hidden = gelu(xn @ W1 + b1) ----------------
    for (int nc = 0; nc < 4; nc++) {
        #pragma unroll
        for (int j = 0; j < 8; j++) {
            int i = tid + 256 * j;
            if (nc < 3) pf[j] = w1p[(nc + 1) * 2048 + i];
            else        pf[j] = w2p[(i >> 4) * 64 + (i & 15)];
        }
        float a1[2][8][4];
        #pragma unroll
        for (int mf = 0; mf < 2; mf++)
            #pragma unroll
            for (int nf = 0; nf < 8; nf++)
                #pragma unroll
                for (int e = 0; e < 4; e++) a1[mf][nf][e] = 0.f;
        #pragma unroll
        for (int k = 0; k < 8; k++) {
            uint32_t a[2][4], b[8][2];
            #pragma unroll
            for (int mf = 0; mf < 2; mf++)
                LDSM4(a[mf][0], a[mf][1], a[mf][2], a[mf][3],
                      Abase + mf * 16 * SA * 2 + k * 32);
            #pragma unroll
            for (int nf2 = 0; nf2 < 4; nf2++) {
                uint32_t r0, r1, r2, r3;
                LDSM4(r0, r1, r2, r3, Bbase + nf2 * 16 * SA * 2 + k * 32);
                b[nf2 * 2][0] = r0; b[nf2 * 2][1] = r2;
                b[nf2 * 2 + 1][0] = r1; b[nf2 * 2 + 1][1] = r3;
            }
            #pragma unroll
            for (int mf = 0; mf < 2; mf++)
                #pragma unroll
                for (int nf = 0; nf < 8; nf++) MMA16816(a1[mf][nf], a[mf], b[nf]);
        }
        #pragma unroll
        for (int mf = 0; mf < 2; mf++)
            #pragma unroll
            for (int nf = 0; nf < 8; nf++) {
                int nl = wn * 64 + nf * 8 + t4 * 2;
                int ng = nc * 128 + nl;
                int r0 = wm * 32 + mf * 16 + quad;
                #pragma unroll
                for (int hrow = 0; hrow < 2; hrow++) {
                    float v0 = a1[mf][nf][hrow * 2] + sb1[ng];
                    float v1 = a1[mf][nf][hrow * 2 + 1] + sb1[ng + 1];
                    float t0 = tanh_fast(0.7978845608028654f * (v0 + 0.044715f * v0 * v0 * v0));
                    float t1 = tanh_fast(0.7978845608028654f * (v1 + 0.044715f * v1 * v1 * v1));
                    *(bf162*)(Hs + (r0 + hrow * 8) * SH + ng) =
                        __floats2bfloat162_rn(0.5f * v0 * (1.f + t0), 0.5f * v1 * (1.f + t1));
                }
            }
        __syncthreads();
        #pragma unroll
        for (int j = 0; j < 8; j++) {
            int i = tid + 256 * j;
            int r = i >> 4, c = i & 15;
            *(uint4*)(Bs + r * SA + c * 8) = pf[j];
        }
        __syncthreads();
    }

    // ---------------- stage 2: y = hidden @ W2 ----------------
    float acc2[2][8][4];
    #pragma unroll
    for (int mf = 0; mf < 2; mf++)
        #pragma unroll
        for (int nf = 0; nf < 8; nf++)
            #pragma unroll
            for (int e = 0; e < 4; e++) acc2[mf][nf][e] = 0.f;

    for (int kc = 0; kc < 4; kc++) {
        if (kc < 3) {
            #pragma unroll
            for (int j = 0; j < 8; j++) {
                int i = tid + 256 * j;
                pf[j] = w2p[(size_t)(i >> 4) * 64 + (kc + 1) * 16 + (i & 15)];
            }
        }
        #pragma unroll
        for (int k = 0; k < 8; k++) {
            uint32_t a[2][4], b[8][2];
            #pragma unroll
            for (int mf = 0; mf < 2; mf++)
                LDSM4(a[mf][0], a[mf][1], a[mf][2], a[mf][3],
                      Hbase + mf * 16 * SH * 2 + kc * 256 + k * 32);
            #pragma unroll
            for (int nf2 = 0; nf2 < 4; nf2++) {
                uint32_t r0, r1, r2, r3;
                LDSM4(r0, r1, r2, r3, Bbase + nf2 * 16 * SA * 2 + k * 32);
                b[nf2 * 2][0] = r0; b[nf2 * 2][1] = r2;
                b[nf2 * 2 + 1][0] = r1; b[nf2 * 2 + 1][1] = r3;
            }
            #pragma unroll
            for (int mf = 0; mf < 2; mf++)
                #pragma unroll
                for (int nf = 0; nf < 8; nf++) MMA16816(acc2[mf][nf], a[mf], b[nf]);
        }
        if (kc < 3) {
            __syncthreads();
            #pragma unroll
            for (int j = 0; j < 8; j++) {
                int i = tid + 256 * j;
                int r = i >> 4, c = i & 15;
                *(uint4*)(Bs + r * SA + c * 8) = pf[j];
            }
            __syncthreads();
        }
    }

    // ---------------- epilogue ----------------
    #pragma unroll
    for (int mf = 0; mf < 2; mf++)
        #pragma unroll
        for (int nf = 0; nf < 8; nf++) {
            int n = wn * 64 + nf * 8 + t4 * 2;
            size_t r0 = m0 + wm * 32 + mf * 16 + quad;
            #pragma unroll
            for (int hrow = 0; hrow < 2; hrow++) {
                size_t r = r0 + hrow * 8;
                float v0 = (acc2[mf][nf][hrow * 2] + sb2[n]) * sgm[n] + x[r * 128 + n];
                float v1 = (acc2[mf][nf][hrow * 2 + 1] + sb2[n + 1]) * sgm[n + 1] + x[r * 128 + n + 1];
                out[r * 128 + n] = v0;
                out[r * 128 + n + 1] = v1;
            }
        }
}

// ---------------------------------------------------------------------------
extern "C" void kernel_launch(void* const* d_in, const int* in_sizes, int n_in,
                              void* d_out, int out_size) {
    const float* x     = (const float*)d_in[0];
    const float* Wg    = (const float*)d_in[1];
    const float* bg    = (const float*)d_in[2];
    const float* Wh    = (const float*)d_in[3];
    const float* bh    = (const float*)d_in[4];
    const float* gk    = (const float*)d_in[5];
    const float* hk    = (const float*)d_in[6];
    const float* Wo    = (const float*)d_in[7];
    const float* bo    = (const float*)d_in[8];
    const float* lns   = (const float*)d_in[9];
    const float* lnb   = (const float*)d_in[10];
    const float* W1    = (const float*)d_in[11];
    const float* b1    = (const float*)d_in[12];
    const float* W2    = (const float*)d_in[13];
    const float* b2    = (const float*)d_in[14];
    const float* gamma = (const float*)d_in[15];
    float* out = (float*)d_out;

    cudaFuncSetAttribute(k_proj,  cudaFuncAttributeMaxDynamicSharedMemorySize, PROJ_SMEM);
    cudaFuncSetAttribute(k_womlp, cudaFuncAttributeMaxDynamicSharedMemorySize, WM_SMEM);

    k_prep<<<256, 256>>>(Wg, Wh, Wo, W1, W2, gk, hk);
    k_proj<<<NTILES, 128, PROJ_SMEM>>>(x, bg, bh);
    k_conv<<<dim3(4, Bb * Hh, 2), 256>>>();
    k_scan<<<(Bb * Hh * Ww * 64) / 256, 256>>>();
    k_womlp<<<NTILES, 256, WM_SMEM>>>(x, bo, lns, lnb, b1, b2, gamma, out);
}

// round 8
// speedup vs baseline: 3.6233x; 1.0732x over previous
#include <cuda_runtime.h>
#include <cuda_bf16.h>
#include <math.h>
#include <stdint.h>

#define Bb 2
#define Tt 16
#define Hh 56
#define Ww 56
#define Cc 128
#define NPTS (Bb*Tt*Hh*Ww)          /* 100352 */
#define TOT  (NPTS*Cc)              /* 12845056 */
#define HWC  (Hh*Ww*Cc)
#define KTAPS 245
#define NTILES (NPTS/128)           /* 784 */

typedef __nv_bfloat16 bf16;
typedef __nv_bfloat162 bf162;

// ---------------- device scratch (allocation-free) ----------------
__device__ __align__(16) bf16 g_gateP[TOT];
__device__ __align__(16) bf16 g_hidP[TOT];
__device__ __align__(16) bf16 g_gateS[TOT];
__device__ __align__(16) bf16 g_hidS[TOT];
__device__ __align__(16) bf16 g_E[TOT];
__device__ __align__(16) bf16 g_WgT[Cc*Cc];       // [n][k]
__device__ __align__(16) bf16 g_WhT[Cc*Cc];
__device__ __align__(16) bf16 g_WoT[Cc*Cc];
__device__ __align__(16) bf16 g_W1T[512*Cc];      // [n=512][k=128]
__device__ __align__(16) bf16 g_W2T[Cc*512];      // [n=128][k=512]
__device__ __align__(16) bf16 g_kB[2][KTAPS*Cc];  // [tap][c]

// ---------------- helpers ----------------
__device__ __forceinline__ uint32_t smem_u32(const void* p) {
    uint32_t a;
    asm("{ .reg .u64 t; cvta.to.shared.u64 t, %1; cvt.u32.u64 %0, t; }" : "=r"(a) : "l"(p));
    return a;
}
#define LDSM4(r0, r1, r2, r3, a) \
    asm volatile("ldmatrix.sync.aligned.m8n8.x4.shared.b16 {%0,%1,%2,%3}, [%4];" \
        : "=r"(r0), "=r"(r1), "=r"(r2), "=r"(r3) : "r"(a))
#define MMA16816(c, a, b) \
    asm volatile("mma.sync.aligned.m16n8k16.row.col.f32.bf16.bf16.f32 " \
        "{%0,%1,%2,%3},{%4,%5,%6,%7},{%8,%9},{%0,%1,%2,%3};" \
        : "+f"((c)[0]), "+f"((c)[1]), "+f"((c)[2]), "+f"((c)[3]) \
        : "r"((a)[0]), "r"((a)[1]), "r"((a)[2]), "r"((a)[3]), "r"((b)[0]), "r"((b)[1]))

__device__ __forceinline__ float tanh_fast(float x) {
    float y;
    asm("tanh.approx.f32 %0, %1;" : "=f"(y) : "f"(x));
    return y;
}
__device__ __forceinline__ float exp_fast(float x) {
    float y;
    asm("ex2.approx.f32 %0, %1;" : "=f"(y) : "f"(x * 1.4426950408889634f));
    return y;
}
__device__ __forceinline__ float rcp_fast(float x) {
    float y;
    asm("rcp.approx.f32 %0, %1;" : "=f"(y) : "f"(x));
    return y;
}

#define SA 136    /* smem row stride (bf16 elems) for 128-col tiles */
#define SH 520    /* smem row stride for hidden (512-col) tile */

// ---------------------------------------------------------------------------
// K0: weight prep
// ---------------------------------------------------------------------------
__global__ void k_prep(const float* __restrict__ Wg, const float* __restrict__ Wh,
                       const float* __restrict__ Wo, const float* __restrict__ W1,
                       const float* __restrict__ W2, const float* __restrict__ gk,
                       const float* __restrict__ hk) {
    int i = blockIdx.x * 256 + threadIdx.x;
    if (i < 16384) {
        int n = i >> 7, k = i & 127;
        g_WgT[i] = __float2bfloat16(Wg[k * 128 + n]);
        g_WhT[i] = __float2bfloat16(Wh[k * 128 + n]);
        g_WoT[i] = __float2bfloat16(Wo[k * 128 + n]);
    }
    if (i < 65536) {
        int n = i >> 7, k = i & 127;
        g_W1T[i] = __float2bfloat16(W1[k * 512 + n]);
        int n2 = i >> 9, k2 = i & 511;
        g_W2T[i] = __float2bfloat16(W2[k2 * 128 + n2]);
    }
    if (i < 2 * KTAPS * 128) {
        int which = i / (KTAPS * 128);
        int j = i - which * (KTAPS * 128);
        int tap = j >> 7, c = j & 127;
        const float* s = which ? hk : gk;
        g_kB[which][j] = __float2bfloat16(s[c * KTAPS + tap]);
    }
}

// ---------------------------------------------------------------------------
// K1: dual projection, 256 threads (8 warps: which x wn(4), 32 cols each)
// ---------------------------------------------------------------------------
#define PROJ_SMEM (3*128*SA*2 + 256*4)
__global__ void __launch_bounds__(256) k_proj(const float* __restrict__ x,
                                              const float* __restrict__ bg,
                                              const float* __restrict__ bh) {
    extern __shared__ __align__(16) char sm[];
    bf16* As = (bf16*)sm;
    bf16* Bs = As + 128 * SA;
    float* sbias = (float*)(Bs + 2 * 128 * SA);
    int tid = threadIdx.x, w = tid >> 5, l = tid & 31;
    size_t m0 = (size_t)blockIdx.x * 128;
    if (tid < 128) sbias[tid] = bg[tid];
    else           sbias[tid] = bh[tid - 128];

    const float2* xs = (const float2*)(x + m0 * 128);
    for (int idx = tid; idx < 128 * 64; idx += 256) {
        int r = idx >> 6, cp = idx & 63;
        float2 v = xs[idx];
        *(bf162*)(As + r * SA + cp * 2) = __floats2bfloat162_rn(v.x, v.y);
    }
    const uint4* wgp = (const uint4*)g_WgT;
    const uint4* whp = (const uint4*)g_WhT;
    for (int idx = tid; idx < 128 * 16; idx += 256) {
        int r = idx >> 4, c = idx & 15;
        *(uint4*)(Bs + r * SA + c * 8) = wgp[idx];
        *(uint4*)(Bs + 128 * SA + r * SA + c * 8) = whp[idx];
    }
    __syncthreads();

    int which = w >> 2;
    int wn0 = (w & 3) * 32;
    uint32_t Abase = smem_u32(As) + ((l & 15) * SA + (l >> 4) * 8) * 2;
    uint32_t Bbase = smem_u32(Bs + which * 128 * SA) + ((l & 15) * SA + (l >> 4) * 8) * 2 + wn0 * SA * 2;
    bf16* outb = which ? g_hidP : g_gateP;
    float* bb = sbias + which * 128;
    int quad = l >> 2, t4 = l & 3;

    for (int mc = 0; mc < 4; mc++) {
        float acc[2][4][4];
        #pragma unroll
        for (int mf = 0; mf < 2; mf++)
            #pragma unroll
            for (int nf = 0; nf < 4; nf++)
                #pragma unroll
                for (int e = 0; e < 4; e++) acc[mf][nf][e] = 0.f;
        #pragma unroll
        for (int k = 0; k < 8; k++) {
            uint32_t a[2][4], b[4][2];
            #pragma unroll
            for (int mf = 0; mf < 2; mf++)
                LDSM4(a[mf][0], a[mf][1], a[mf][2], a[mf][3],
                      Abase + (mc * 32 + mf * 16) * SA * 2 + k * 32);
            #pragma unroll
            for (int nf2 = 0; nf2 < 2; nf2++) {
                uint32_t r0, r1, r2, r3;
                LDSM4(r0, r1, r2, r3, Bbase + nf2 * 16 * SA * 2 + k * 32);
                b[nf2 * 2][0] = r0; b[nf2 * 2][1] = r2;
                b[nf2 * 2 + 1][0] = r1; b[nf2 * 2 + 1][1] = r3;
            }
            #pragma unroll
            for (int mf = 0; mf < 2; mf++)
                #pragma unroll
                for (int nf = 0; nf < 4; nf++) MMA16816(acc[mf][nf], a[mf], b[nf]);
        }
        #pragma unroll
        for (int mf = 0; mf < 2; mf++)
            #pragma unroll
            for (int nf = 0; nf < 4; nf++) {
                int n = wn0 + nf * 8 + t4 * 2;
                int r0 = mc * 32 + mf * 16 + quad;
                *(bf162*)(outb + (m0 + r0) * 128 + n) =
                    __floats2bfloat162_rn(acc[mf][nf][0] + bb[n], acc[mf][nf][1] + bb[n + 1]);
                *(bf162*)(outb + (m0 + r0 + 8) * 128 + n) =
                    __floats2bfloat162_rn(acc[mf][nf][2] + bb[n], acc[mf][nf][3] + bb[n + 1]);
            }
    }
}

// ---------------------------------------------------------------------------
// K2: depthwise circular conv 5x7x7 with t-reuse (unchanged)
// ---------------------------------------------------------------------------
__global__ void __launch_bounds__(256) k_conv(void) {
    int ct = threadIdx.x & 63;
    int tq = threadIdx.x >> 6;
    int which = blockIdx.z;
    const uint32_t* __restrict__ in = (const uint32_t*)(which ? g_hidP : g_gateP);
    uint32_t* __restrict__ outp = (uint32_t*)(which ? g_hidS : g_gateS);
    const uint32_t* __restrict__ kt = (const uint32_t*)g_kB[which];
    int w0 = blockIdx.x * 14;
    int by = blockIdx.y;
    int h = by % Hh;
    int b = by / Hh;
    int t0 = tq * 4;

    int offs[20];
    #pragma unroll
    for (int j = 0; j < 20; j++) {
        int wi = w0 - 3 + j;
        if (wi < 0)   wi += 56;
        if (wi >= 56) wi -= 56;
        offs[j] = wi * 64;
    }

    bf162 acc[4][14];
    bf162 z = __floats2bfloat162_rn(0.f, 0.f);
    #pragma unroll
    for (int tr = 0; tr < 4; tr++)
        #pragma unroll
        for (int i = 0; i < 14; i++) acc[tr][i] = z;

    for (int kh = 0; kh < 7; kh++) {
        int hin = h - kh + 3;
        if (hin < 0)   hin += 56;
        if (hin >= 56) hin -= 56;
        uint32_t kv[5][7];
        #pragma unroll
        for (int ktp = 0; ktp < 5; ktp++)
            #pragma unroll
            for (int kw = 0; kw < 7; kw++)
                kv[ktp][kw] = kt[(size_t)(ktp * 49 + kh * 7 + kw) * 64 + ct];

        #pragma unroll
        for (int j = 0; j < 8; j++) {
            int t_in = (t0 - 2 + j) & 15;
            const uint32_t* src = in + (size_t)((b * 16 + t_in) * Hh + hin) * (Ww * 64) + ct;
            uint32_t win[20];
            #pragma unroll
            for (int jj = 0; jj < 20; jj++) win[jj] = src[offs[jj]];
            #pragma unroll
            for (int ktp = 0; ktp < 5; ktp++) {
                int tr = j + ktp - 4;
                if (tr >= 0 && tr < 4) {
                    #pragma unroll
                    for (int i = 0; i < 14; i++) {
                        #pragma unroll
                        for (int kw = 0; kw < 7; kw++)
                            acc[tr][i] = __hfma2(*(bf162*)&kv[ktp][kw],
                                                 *(bf162*)&win[i + 6 - kw],
                                                 acc[tr][i]);
                    }
                }
            }
        }
    }
    #pragma unroll
    for (int tr = 0; tr < 4; tr++) {
        uint32_t* dst = outp + (size_t)(((b * 16 + t0 + tr) * Hh + h) * Ww + w0) * 64 + ct;
        #pragma unroll
        for (int i = 0; i < 14; i++)
            dst[(size_t)i * 64] = *(uint32_t*)&acc[tr][i];
    }
}

// ---------------------------------------------------------------------------
// K3: LINEAR-domain Heinsen scan (unchanged)
// ---------------------------------------------------------------------------
__global__ void k_scan(void) {
    int idx = blockIdx.x * 256 + threadIdx.x;
    int cp = idx & 63;
    int rest = idx >> 6;
    int w = rest % 56; rest /= 56;
    int h = rest % 56;
    int b = rest / 56;
    size_t base = (((size_t)(b * Tt) * Hh + h) * Ww + w) * 64 + cp;
    const uint32_t* gp = (const uint32_t*)g_gateS;
    const uint32_t* hp = (const uint32_t*)g_hidS;
    uint32_t* ep = (uint32_t*)g_E;
    float H0 = 0.f, H1 = 0.f;
    #pragma unroll
    for (int t = 0; t < Tt; t++) {
        size_t off = base + (size_t)t * (HWC / 2);
        uint32_t gu = gp[off], hu = hp[off];
        float2 g2 = __bfloat1622float2(*(bf162*)&gu);
        float2 h2 = __bfloat1622float2(*(bf162*)&hu);
        float e0 = exp_fast(-fabsf(g2.x));
        float r0 = rcp_fast(1.f + e0);
        float s0 = (g2.x >= 0.f) ? r0 : e0 * r0;
        float f0 = (g2.x >= 0.f) ? e0 * r0 : r0;
        float v0 = (h2.x * h2.x + 1e-6f) * s0;
        H0 = fmaf(f0, H0, v0);
        float e1 = exp_fast(-fabsf(g2.y));
        float r1 = rcp_fast(1.f + e1);
        float s1 = (g2.y >= 0.f) ? r1 : e1 * r1;
        float f1 = (g2.y >= 0.f) ? e1 * r1 : r1;
        float v1 = (h2.y * h2.y + 1e-6f) * s1;
        H1 = fmaf(f1, H1, v1);
        bf162 o = __floats2bfloat162_rn(H0, H1);
        ep[off] = *(uint32_t*)&o;
    }
}

// ---------------------------------------------------------------------------
// K4: MEGA womlp, 512 threads (16 warps: wm(4) x wn(4), 32 cols each)
// ---------------------------------------------------------------------------
#define WM_SMEM (128*SA*2 + 128*SA*2 + 128*SH*2 + 2432*4)
__global__ void __launch_bounds__(512) k_womlp(const float* __restrict__ x,
                                               const float* __restrict__ bo,
                                               const float* __restrict__ lns,
                                               const float* __restrict__ lnb,
                                               const float* __restrict__ b1,
                                               const float* __restrict__ b2,
                                               const float* __restrict__ gamma,
                                               float* __restrict__ out) {
    extern __shared__ __align__(16) char sm[];
    bf16* As = (bf16*)sm;
    bf16* Bs = As + 128 * SA;
    bf16* Hs = Bs + 128 * SA;
    float* sbo  = (float*)(Hs + 128 * SH);  // 128
    float* slns = sbo + 128;                // 128
    float* slnb = slns + 128;               // 128
    float* sb1  = slnb + 128;               // 512
    float* sb2  = sb1 + 512;                // 128
    float* sgm  = sb2 + 128;                // 128
    float* rs   = sgm + 128;                // 128*4
    float* rq   = rs + 512;                 // 128*4
    float2* stat = (float2*)(rq + 512);     // 128

    int tid = threadIdx.x, w = tid >> 5, l = tid & 31;
    int wm = w >> 2, wn = w & 3;
    int quad = l >> 2, t4 = l & 3;
    size_t m0 = (size_t)blockIdx.x * 128;

    if (tid < 128) {
        sbo[tid] = bo[tid]; slns[tid] = lns[tid]; slnb[tid] = lnb[tid];
        sb2[tid] = b2[tid]; sgm[tid] = gamma[tid];
    }
    if (tid < 512) sb1[tid] = b1[tid];

    const uint4* ep = (const uint4*)(g_E + m0 * 128);
    for (int j = 0; j < 4; j++) {
        int i = tid + 512 * j;
        int r = i >> 4, c = i & 15;
        *(uint4*)(As + r * SA + c * 8) = ep[i];
    }
    {
        const uint4* wop = (const uint4*)g_WoT;
        uint4 pf0[4];
        #pragma unroll
        for (int j = 0; j < 4; j++) pf0[j] = wop[tid + 512 * j];
        #pragma unroll
        for (int j = 0; j < 4; j++) {
            int i = tid + 512 * j;
            int r = i >> 4, c = i & 15;
            *(uint4*)(Bs + r * SA + c * 8) = pf0[j];
        }
    }
    __syncthreads();

    uint32_t Abase = smem_u32(As) + ((l & 15) * SA + (l >> 4) * 8) * 2 + (wm * 32) * SA * 2;
    uint32_t Bbase = smem_u32(Bs) + ((l & 15) * SA + (l >> 4) * 8) * 2 + (wn * 32) * SA * 2;
    uint32_t Hbase = smem_u32(Hs) + ((l & 15) * SH + (l >> 4) * 8) * 2 + (wm * 32) * SH * 2;

    const uint4* w1p = (const uint4*)g_W1T;
    const uint4* w2p = (const uint4*)g_W2T;
    uint4 pf[4];

    // ---------------- stage 0: wo GEMM ----------------
    #pragma unroll
    for (int j = 0; j < 4; j++) pf[j] = w1p[tid + 512 * j];

    float acc[2][4][4];
    #pragma unroll
    for (int mf = 0; mf < 2; mf++)
        #pragma unroll
        for (int nf = 0; nf < 4; nf++)
            #pragma unroll
            for (int e = 0; e < 4; e++) acc[mf][nf][e] = 0.f;
    #pragma unroll
    for (int k = 0; k < 8; k++) {
        uint32_t a[2][4], b[4][2];
        #pragma unroll
        for (int mf = 0; mf < 2; mf++)
            LDSM4(a[mf][0], a[mf][1], a[mf][2], a[mf][3],
                  Abase + mf * 16 * SA * 2 + k * 32);
        #pragma unroll
        for (int nf2 = 0; nf2 < 2; nf2++) {
            uint32_t r0, r1, r2, r3;
            LDSM4(r0, r1, r2, r3, Bbase + nf2 * 16 * SA * 2 + k * 32);
            b[nf2 * 2][0] = r0; b[nf2 * 2][1] = r2;
            b[nf2 * 2 + 1][0] = r1; b[nf2 * 2 + 1][1] = r3;
        }
        #pragma unroll
        for (int mf = 0; mf < 2; mf++)
            #pragma unroll
            for (int nf = 0; nf < 4; nf++) MMA16816(acc[mf][nf], a[mf], b[nf]);
    }

    #pragma unroll
    for (int mf = 0; mf < 2; mf++) {
        float s0 = 0.f, q0 = 0.f, s1 = 0.f, q1 = 0.f;
        #pragma unroll
        for (int nf = 0; nf < 4; nf++) {
            int n = wn * 32 + nf * 8 + t4 * 2;
            float v0 = acc[mf][nf][0] + sbo[n];
            float v1 = acc[mf][nf][1] + sbo[n + 1];
            float v2 = acc[mf][nf][2] + sbo[n];
            float v3 = acc[mf][nf][3] + sbo[n + 1];
            acc[mf][nf][0] = v0; acc[mf][nf][1] = v1;
            acc[mf][nf][2] = v2; acc[mf][nf][3] = v3;
            s0 += v0 + v1; q0 += v0 * v0 + v1 * v1;
            s1 += v2 + v3; q1 += v2 * v2 + v3 * v3;
        }
        #pragma unroll
        for (int o = 1; o < 4; o <<= 1) {
            s0 += __shfl_xor_sync(0xffffffffu, s0, o);
            q0 += __shfl_xor_sync(0xffffffffu, q0, o);
            s1 += __shfl_xor_sync(0xffffffffu, s1, o);
            q1 += __shfl_xor_sync(0xffffffffu, q1, o);
        }
        if (t4 == 0) {
            int rA = wm * 32 + mf * 16 + quad;
            rs[rA * 4 + wn] = s0; rq[rA * 4 + wn] = q0;
            rs[(rA + 8) * 4 + wn] = s1; rq[(rA + 8) * 4 + wn] = q1;
        }
    }
    __syncthreads();

    #pragma unroll
    for (int j = 0; j < 4; j++) {
        int i = tid + 512 * j;
        int r = i >> 4, c = i & 15;
        *(uint4*)(Bs + r * SA + c * 8) = pf[j];
    }
    if (tid < 128) {
        float mean = (rs[tid * 4] + rs[tid * 4 + 1] + rs[tid * 4 + 2] + rs[tid * 4 + 3]) * (1.f / 128.f);
        float var = (rq[tid * 4] + rq[tid * 4 + 1] + rq[tid * 4 + 2] + rq[tid * 4 + 3]) * (1.f / 128.f) - mean * mean;
        stat[tid] = make_float2(mean, rsqrtf(var + 1e-6f));
    }
    __syncthreads();

    #pragma unroll
    for (int mf = 0; mf < 2; mf++) {
        int rA = wm * 32 + mf * 16 + quad;
        float2 stA = stat[rA], stB = stat[rA + 8];
        #pragma unroll
        for (int nf = 0; nf < 4; nf++) {
            int n = wn * 32 + nf * 8 + t4 * 2;
            float x0 = (acc[mf][nf][0] - stA.x) * stA.y * slns[n] + slnb[n];
            float x1 = (acc[mf][nf][1] - stA.x) * stA.y * slns[n + 1] + slnb[n + 1];
            float x2 = (acc[mf][nf][2] - stB.x) * stB.y * slns[n] + slnb[n];
            float x3 = (acc[mf][nf][3] - stB.x) * stB.y * slns[n + 1] + slnb[n + 1];
            *(bf162*)(As + rA * SA + n) = __floats2bfloat162_rn(x0, x1);
            *(bf162*)(As + (rA + 8) * SA + n) = __floats2bfloat162_rn(x2, x3);
        }
    }
    __syncthreads();

    // ---------------- stage 1: hidden = gelu(xn @ W1 + b1) ----------------
    for (int nc = 0; nc < 4; nc++) {
        #pragma unroll
        for (int j = 0; j < 4; j++) {
            int i = tid + 512 * j;
            if (nc < 3) pf[j] = w1p[(nc + 1) * 2048 + i];
            else        pf[j] = w2p[(i >> 4) * 64 + (i & 15)];
        }
        float a1[2][4][4];
        #pragma unroll
        for (int mf = 0; mf < 2; mf++)
            #pragma unroll
            for (int nf = 0; nf < 4; nf++)
                #pragma unroll
                for (int e = 0; e < 4; e++) a1[mf][nf][e] = 0.f;
        #pragma unroll
        for (int k = 0; k < 8; k++) {
            uint32_t a[2][4], b[4][2];
            #pragma unroll
            for (int mf = 0; mf < 2; mf++)
                LDSM4(a[mf][0], a[mf][1], a[mf][2], a[mf][3],
                      Abase + mf * 16 * SA * 2 + k * 32);
            #pragma unroll
            for (int nf2 = 0; nf2 < 2; nf2++) {
                uint32_t r0, r1, r2, r3;
                LDSM4(r0, r1, r2, r3, Bbase + nf2 * 16 * SA * 2 + k * 32);
                b[nf2 * 2][0] = r0; b[nf2 * 2][1] = r2;
                b[nf2 * 2 + 1][0] = r1; b[nf2 * 2 + 1][1] = r3;
            }
            #pragma unroll
            for (int mf = 0; mf < 2; mf++)
                #pragma unroll
                for (int nf = 0; nf < 4; nf++) MMA16816(a1[mf][nf], a[mf], b[nf]);
        }
        #pragma unroll
        for (int mf = 0; mf < 2; mf++)
            #pragma unroll
            for (int nf = 0; nf < 4; nf++) {
                int nl = wn * 32 + nf * 8 + t4 * 2;
                int ng = nc * 128 + nl;
                int r0 = wm * 32 + mf * 16 + quad;
                #pragma unroll
                for (int hrow = 0; hrow < 2; hrow++) {
                    float v0 = a1[mf][nf][hrow * 2] + sb1[ng];
                    float v1 = a1[mf][nf][hrow * 2 + 1] + sb1[ng + 1];
                    float t0 = tanh_fast(0.7978845608028654f * (v0 + 0.044715f * v0 * v0 * v0));
                    float t1 = tanh_fast(0.7978845608028654f * (v1 + 0.044715f * v1 * v1 * v1));
                    *(bf162*)(Hs + (r0 + hrow * 8) * SH + ng) =
                        __floats2bfloat162_rn(0.5f * v0 * (1.f + t0), 0.5f * v1 * (1.f + t1));
                }
            }
        __syncthreads();
        #pragma unroll
        for (int j = 0; j < 4; j++) {
            int i = tid + 512 * j;
            int r = i >> 4, c = i & 15;
            *(uint4*)(Bs + r * SA + c * 8) = pf[j];
        }
        __syncthreads();
    }

    // ---------------- stage 2: y = hidden @ W2 ----------------
    float acc2[2][4][4];
    #pragma unroll
    for (int mf = 0; mf < 2; mf++)
        #pragma unroll
        for (int nf = 0; nf < 4; nf++)
            #pragma unroll
            for (int e = 0; e < 4; e++) acc2[mf][nf][e] = 0.f;

    for (int kc = 0; kc < 4; kc++) {
        if (kc < 3) {
            #pragma unroll
            for (int j = 0; j < 4; j++) {
                int i = tid + 512 * j;
                pf[j] = w2p[(size_t)(i >> 4) * 64 + (kc + 1) * 16 + (i & 15)];
            }
        }
        #pragma unroll
        for (int k = 0; k < 8; k++) {
            uint32_t a[2][4], b[4][2];
            #pragma unroll
            for (int mf = 0; mf < 2; mf++)
                LDSM4(a[mf][0], a[mf][1], a[mf][2], a[mf][3],
                      Hbase + mf * 16 * SH * 2 + kc * 256 + k * 32);
            #pragma unroll
            for (int nf2 = 0; nf2 < 2; nf2++) {
                uint32_t r0, r1, r2, r3;
                LDSM4(r0, r1, r2, r3, Bbase + nf2 * 16 * SA * 2 + k * 32);
                b[nf2 * 2][0] = r0; b[nf2 * 2][1] = r2;
                b[nf2 * 2 + 1][0] = r1; b[nf2 * 2 + 1][1] = r3;
            }
            #pragma unroll
            for (int mf = 0; mf < 2; mf++)
                #pragma unroll
                for (int nf = 0; nf < 4; nf++) MMA16816(acc2[mf][nf], a[mf], b[nf]);
        }
        if (kc < 3) {
            __syncthreads();
            #pragma unroll
            for (int j = 0; j < 4; j++) {
                int i = tid + 512 * j;
                int r = i >> 4, c = i & 15;
                *(uint4*)(Bs + r * SA + c * 8) = pf[j];
            }
            __syncthreads();
        }
    }

    // ---------------- epilogue ----------------
    #pragma unroll
    for (int mf = 0; mf < 2; mf++)
        #pragma unroll
        for (int nf = 0; nf < 4; nf++) {
            int n = wn * 32 + nf * 8 + t4 * 2;
            size_t r0 = m0 + wm * 32 + mf * 16 + quad;
            #pragma unroll
            for (int hrow = 0; hrow < 2; hrow++) {
                size_t r = r0 + hrow * 8;
                float v0 = (acc2[mf][nf][hrow * 2] + sb2[n]) * sgm[n] + x[r * 128 + n];
                float v1 = (acc2[mf][nf][hrow * 2 + 1] + sb2[n + 1]) * sgm[n + 1] + x[r * 128 + n + 1];
                out[r * 128 + n] = v0;
                out[r * 128 + n + 1] = v1;
            }
        }
}

// ---------------------------------------------------------------------------
extern "C" void kernel_launch(void* const* d_in, const int* in_sizes, int n_in,
                              void* d_out, int out_size) {
    const float* x     = (const float*)d_in[0];
    const float* Wg    = (const float*)d_in[1];
    const float* bg    = (const float*)d_in[2];
    const float* Wh    = (const float*)d_in[3];
    const float* bh    = (const float*)d_in[4];
    const float* gk    = (const float*)d_in[5];
    const float* hk    = (const float*)d_in[6];
    const float* Wo    = (const float*)d_in[7];
    const float* bo    = (const float*)d_in[8];
    const float* lns   = (const float*)d_in[9];
    const float* lnb   = (const float*)d_in[10];
    const float* W1    = (const float*)d_in[11];
    const float* b1    = (const float*)d_in[12];
    const float* W2    = (const float*)d_in[13];
    const float* b2    = (const float*)d_in[14];
    const float* gamma = (const float*)d_in[15];
    float* out = (float*)d_out;

    cudaFuncSetAttribute(k_proj,  cudaFuncAttributeMaxDynamicSharedMemorySize, PROJ_SMEM);
    cudaFuncSetAttribute(k_womlp, cudaFuncAttributeMaxDynamicSharedMemorySize, WM_SMEM);

    k_prep<<<256, 256>>>(Wg, Wh, Wo, W1, W2, gk, hk);
    k_proj<<<NTILES, 256, PROJ_SMEM>>>(x, bg, bh);
    k_conv<<<dim3(4, Bb * Hh, 2), 256>>>();
    k_scan<<<(Bb * Hh * Ww * 64) / 256, 256>>>();
    k_womlp<<<NTILES, 512, WM_SMEM>>>(x, bo, lns, lnb, b1, b2, gamma, out);
}